// round 11
// baseline (speedup 1.0000x reference)
#include <cuda_runtime.h>
#include <math.h>
#include <stdint.h>

#define BATCH 512
#define CH    256
#define CLS   60
#define MEMSZ 684
#define BR    41040
#define POSN  128
#define NEGN  512
#define NWORDS 1283          // ceil(BR/32)
#define CAPN  2048
#define SAMPN 1024
#define QCOLS 10260          // BR/4
#define QGROUPS 2565         // QCOLS/4
#define QGPAD 2816           // 11*256

typedef unsigned long long u64;

// ------------------------- device scratch -----------------------------------
__device__ float    g_pairs[(size_t)BATCH * BR];   // 84 MB
__device__ uint32_t g_flagbits[NWORDS];            // flag>0 only
__device__ uint32_t g_enqbits[NWORDS];             // enqueued columns
__device__ uint32_t g_validbits[NWORDS];           // flag | enq
__device__ uint32_t g_eqtab[CLS * 15];
__device__ float    g_samp[BATCH * SAMPN];
__device__ float    g_thrH[BATCH], g_thrR[BATCH];
__device__ uint32_t g_listH[(size_t)BATCH * CAPN];
__device__ u64      g_listR[(size_t)BATCH * CAPN];
__device__ int      g_cntH[BATCH], g_cntR[BATCH];
__device__ float    g_posvals[BATCH * MEMSZ];
__device__ double   g_loss;

// ------------------------- helpers ------------------------------------------
__device__ __forceinline__ uint32_t fkey(float v) {
    uint32_t u = __float_as_uint(v);
    return (u & 0x80000000u) ? ~u : (u | 0x80000000u);
}
__device__ __forceinline__ float unfkey(uint32_t u) {
    uint32_t b = (u & 0x80000000u) ? (u & 0x7FFFFFFFu) : ~u;
    return __uint_as_float(b);
}
__device__ __forceinline__ int warpRedInt(int c) {
#pragma unroll
    for (int o = 16; o > 0; o >>= 1) c += __shfl_xor_sync(0xffffffffu, c, o);
    return c;
}
__device__ __forceinline__ float warpRedF(float v) {
#pragma unroll
    for (int o = 16; o > 0; o >>= 1) v += __shfl_xor_sync(0xffffffffu, v, o);
    return v;
}
__device__ __forceinline__ int warpIncScan(int v) {
#pragma unroll
    for (int o = 1; o < 32; o <<= 1) {
        int y = __shfl_up_sync(0xffffffffu, v, o);
        if ((threadIdx.x & 31) >= o) v += y;
    }
    return v;
}

// ------------------------- prep ---------------------------------------------
__global__ void prep_kernel(const float* __restrict__ flag) {
    int i = blockIdx.x * blockDim.x + threadIdx.x;
    if (i == 0) g_loss = 0.0;
    if (i < CLS * 15) {
        int lbl = i / 15, p = i % 15;
        int off = (32 * p) % 60;
        uint32_t m = 0;
        for (int b = 0; b < 32; b++) if ((off + b) % 60 == lbl) m |= 1u << b;
        g_eqtab[i] = m;
    }
    if (i < NWORDS) {
        uint32_t m = 0; int base = i * 32;
        for (int b = 0; b < 32; b++) {
            int j = base + b;
            if (j < BR && flag[j] > 0.f) m |= 1u << b;
        }
        g_flagbits[i] = m;
        g_validbits[i] = m;
        g_enqbits[i] = 0;
    }
    if (i < BATCH) { g_cntH[i] = 0; g_cntR[i] = 0; }
    if (i < BATCH * MEMSZ) g_posvals[i] = INFINITY;
}

__global__ void scatter_kernel(const int* __restrict__ eidx) {
    int m = blockIdx.x * blockDim.x + threadIdx.x;
    if (m < BATCH) {
        int j = eidx[m];
        uint32_t bit = 1u << (j & 31);
        atomicOr(&g_validbits[j >> 5], bit);
        atomicOr(&g_enqbits[j >> 5], bit);
    }
}

// ------- sample GEMM: S_samp[n][s] = F[n] . bank[37s+11], fp32 --------------
__global__ __launch_bounds__(256) void samp_gemm_kernel(const float* __restrict__ F,
                                                        const float* __restrict__ B) {
    __shared__ float As[64][33];
    __shared__ float Bs[64][33];
    const int bj = blockIdx.x * 64;   // sample col base
    const int bn = blockIdx.y * 64;   // row base
    const int tid = threadIdx.x;
    const int tx = tid & 15, ty = tid >> 4;
    float acc[4][4] = {};

    for (int k0 = 0; k0 < CH; k0 += 32) {
#pragma unroll
        for (int l = 0; l < 2; l++) {
            int idx = tid + l * 256;
            int r = idx >> 3;
            int c = (idx & 7) << 2;
            float4 v = *(const float4*)&F[(size_t)(bn + r) * CH + k0 + c];
            As[r][c] = v.x; As[r][c + 1] = v.y; As[r][c + 2] = v.z; As[r][c + 3] = v.w;
            int j = 37 * (bj + r) + 11;
            float4 w = *(const float4*)&B[(size_t)j * CH + k0 + c];
            Bs[r][c] = w.x; Bs[r][c + 1] = w.y; Bs[r][c + 2] = w.z; Bs[r][c + 3] = w.w;
        }
        __syncthreads();
#pragma unroll
        for (int kk = 0; kk < 32; kk++) {
            float a[4], b[4];
#pragma unroll
            for (int i = 0; i < 4; i++) a[i] = As[ty * 4 + i][kk];
#pragma unroll
            for (int j = 0; j < 4; j++) b[j] = Bs[tx * 4 + j][kk];
#pragma unroll
            for (int i = 0; i < 4; i++)
#pragma unroll
                for (int j = 0; j < 4; j++) acc[i][j] += a[i] * b[j];
        }
        __syncthreads();
    }
#pragma unroll
    for (int i = 0; i < 4; i++)
#pragma unroll
        for (int j = 0; j < 4; j++)
            g_samp[(size_t)(bn + ty * 4 + i) * SAMPN + bj + tx * 4 + j] = acc[i][j];
}

// ------- thresh: per-row sampled thresholds, register-resident bisect -------
__global__ __launch_bounds__(256) void thresh_kernel(const int* __restrict__ label,
                                                     const float* __restrict__ rnd) {
    const int wid = threadIdx.x >> 5, lane = threadIdx.x & 31;
    const int n = blockIdx.x * 8 + wid;
    const int lbl = label[n];
    const float* rrow = rnd + (size_t)n * BR;
    uint32_t kH[32], kR[32];
#pragma unroll
    for (int k = 0; k < 32; k++) {
        int s = k * 32 + lane;
        int j = 37 * s + 11;
        int w = j >> 5;
        bool ok = ((g_validbits[w] & ~g_eqtab[lbl * 15 + (w % 15)]) >> (j & 31)) & 1;
        kH[k] = ok ? fkey(g_samp[(size_t)n * SAMPN + s]) : 0u;
        kR[k] = ok ? __float_as_uint(rrow[j]) : 0xFFFFFFFFu;
    }
    {   // rank-32 largest of 1024 samples
        uint32_t lo = 0, hi = 0xFFFFFFFFu;
        while (lo < hi) {
            uint32_t d = hi - lo;
            uint32_t mid = lo + (d >> 1) + (d & 1);
            int c = 0;
#pragma unroll
            for (int k = 0; k < 32; k++) c += (kH[k] >= mid);
            c = warpRedInt(c);
            if (c >= 32) lo = mid; else hi = mid - 1;
        }
        if (lane == 0) g_thrH[n] = unfkey(lo);
    }
    {   // rank-32 smallest of 1024 samples
        uint32_t lo = 0, hi = 0xFFFFFFFFu;
        while (lo < hi) {
            uint32_t mid = lo + ((hi - lo) >> 1);
            int c = 0;
#pragma unroll
            for (int k = 0; k < 32; k++) c += (kR[k] <= mid);
            c = warpRedInt(c);
            if (c >= 32) hi = mid; else lo = mid + 1;
        }
        if (lane == 0) g_thrR[n] = __uint_as_float(lo);
    }
}

// --------------- tf32 GEMM with fused selection epilogue --------------------
#define GBM 128
#define GBN 128
#define GBK 32
#define GPAD 36
#define GKITERS 8

__device__ __forceinline__ void mma_tf32(float* c, const uint32_t* a, const uint32_t* b) {
    asm volatile(
        "mma.sync.aligned.m16n8k8.row.col.f32.tf32.tf32.f32 "
        "{%0,%1,%2,%3},{%4,%5,%6,%7},{%8,%9},{%0,%1,%2,%3};"
        : "+f"(c[0]), "+f"(c[1]), "+f"(c[2]), "+f"(c[3])
        : "r"(a[0]), "r"(a[1]), "r"(a[2]), "r"(a[3]), "r"(b[0]), "r"(b[1]));
}

__global__ __launch_bounds__(128) void gemm_tf32_kernel(const float* __restrict__ F,
                                                        const float* __restrict__ BK_,
                                                        const int* __restrict__ label) {
    extern __shared__ float sm[];
    float* As = sm;
    float* Bs = sm + 2 * GBM * GPAD;
#define ASM(bf, r, c) As[(bf) * GBM * GPAD + (r) * GPAD + (c)]
#define BSM(bf, r, c) Bs[(bf) * GBM * GPAD + (r) * GPAD + (c)]
    __shared__ int   s_lbl[GBM];
    __shared__ float s_thr[GBM];
    __shared__ uint32_t s_epi[4];   // flag & ~enq for this block's 128 columns

    const int bj = blockIdx.x * GBN;
    const int bn = blockIdx.y * GBM;
    const int tid = threadIdx.x;
    const int wid = tid >> 5, lane = tid & 31;
    const int wm = (wid >> 1) * 64, wn = (wid & 1) * 64;
    const int tr = lane >> 2, tc = lane & 3;

    if (tid < GBM) { s_lbl[tid] = label[bn + tid]; s_thr[tid] = g_thrH[bn + tid]; }
    if (tid < 4) {
        int w = (bj >> 5) + tid;
        s_epi[tid] = (w < NWORDS) ? (g_flagbits[w] & ~g_enqbits[w]) : 0u;
    }

    float acc[4][8][4];
#pragma unroll
    for (int i = 0; i < 4; i++)
#pragma unroll
        for (int j = 0; j < 8; j++)
#pragma unroll
            for (int k = 0; k < 4; k++) acc[i][j][k] = 0.f;

    auto load_stage = [&](int buf, int kt) {
        int k0 = kt * GBK;
#pragma unroll
        for (int i = 0; i < 8; i++) {
            int slot = tid + i * 128;
            int r = slot >> 3;
            int kq = (slot & 7) * 4;
            uint32_t da = (uint32_t)__cvta_generic_to_shared(&ASM(buf, r, kq));
            const float* ga = F + (size_t)(bn + r) * CH + k0 + kq;
            asm volatile("cp.async.cg.shared.global [%0], [%1], 16;" :: "r"(da), "l"(ga));
            int j = bj + r;
            int ok = (j < BR) ? 16 : 0;
            const float* gb = BK_ + (size_t)(j < BR ? j : 0) * CH + k0 + kq;
            uint32_t db = (uint32_t)__cvta_generic_to_shared(&BSM(buf, r, kq));
            asm volatile("cp.async.cg.shared.global [%0], [%1], 16, %2;" :: "r"(db), "l"(gb), "r"(ok));
        }
    };

    load_stage(0, 0);
    asm volatile("cp.async.commit_group;");

    for (int kt = 0; kt < GKITERS; kt++) {
        asm volatile("cp.async.wait_group 0;");
        __syncthreads();
        if (kt + 1 < GKITERS) {
            load_stage((kt + 1) & 1, kt + 1);
            asm volatile("cp.async.commit_group;");
        }
        int b = kt & 1;
#pragma unroll
        for (int ks = 0; ks < 4; ks++) {
            int kk = ks * 8;
            uint32_t af[4][4], bf[8][2];
#pragma unroll
            for (int mi = 0; mi < 4; mi++) {
                int r0 = wm + mi * 16 + tr;
                af[mi][0] = __float_as_uint(ASM(b, r0,     kk + tc));
                af[mi][1] = __float_as_uint(ASM(b, r0 + 8, kk + tc));
                af[mi][2] = __float_as_uint(ASM(b, r0,     kk + tc + 4));
                af[mi][3] = __float_as_uint(ASM(b, r0 + 8, kk + tc + 4));
            }
#pragma unroll
            for (int ni = 0; ni < 8; ni++) {
                int r0 = wn + ni * 8 + tr;
                bf[ni][0] = __float_as_uint(BSM(b, r0, kk + tc));
                bf[ni][1] = __float_as_uint(BSM(b, r0, kk + tc + 4));
            }
#pragma unroll
            for (int mi = 0; mi < 4; mi++)
#pragma unroll
                for (int ni = 0; ni < 8; ni++) mma_tf32(acc[mi][ni], af[mi], bf[ni]);
        }
    }

    auto epi = [&](int mrel, int col, float val) {
        if (col >= BR) return;
        uint32_t bit = 1u << (col & 31);
        if (s_epi[(col >> 5) & 3] & bit) {
            int lbl = s_lbl[mrel];
            int m = bn + mrel;
            int r60 = col % 60;
            if (r60 == lbl) {
                g_posvals[m * MEMSZ + (unsigned)(col - lbl) / 60u] = val;
            } else if (val >= s_thr[mrel]) {
                int p = atomicAdd(&g_cntH[m], 1);
                if (p < CAPN) g_listH[(size_t)m * CAPN + p] = fkey(val);
            }
        }
    };

#pragma unroll
    for (int mi = 0; mi < 4; mi++) {
        int mrel0 = wm + mi * 16 + tr;
        int m = bn + mrel0;
        float* p0 = &g_pairs[(size_t)m * BR];
        float* p1 = &g_pairs[(size_t)(m + 8) * BR];
#pragma unroll
        for (int ni = 0; ni < 8; ni++) {
            int col = bj + wn + ni * 8 + tc * 2;
            if (col < BR) {
                *(float2*)(p0 + col) = make_float2(acc[mi][ni][0], acc[mi][ni][1]);
                *(float2*)(p1 + col) = make_float2(acc[mi][ni][2], acc[mi][ni][3]);
            }
            epi(mrel0,     col,     acc[mi][ni][0]);
            epi(mrel0,     col + 1, acc[mi][ni][1]);
            epi(mrel0 + 8, col,     acc[mi][ni][2]);
            epi(mrel0 + 8, col + 1, acc[mi][ni][3]);
        }
    }
#undef ASM
#undef BSM
}

// -------- fixup: S = F @ F^T (fp32), scatter + fused selection push ---------
__global__ __launch_bounds__(256) void fixup_gemm_kernel(const float* __restrict__ F,
                                                         const int* __restrict__ eidx,
                                                         const int* __restrict__ label) {
    __shared__ float As[64][33];
    __shared__ float Bs[64][33];
    __shared__ int   s_col[64];
    __shared__ int   s_lbl[64];
    __shared__ float s_thr[64];
    const int bj = blockIdx.x * 64;   // enqueue slot base
    const int bn = blockIdx.y * 64;   // batch row base
    const int tid = threadIdx.x;
    const int tx = tid & 15, ty = tid >> 4;
    if (tid < 64) {
        s_col[tid] = eidx[bj + tid];
        s_lbl[tid] = label[bn + tid];
        s_thr[tid] = g_thrH[bn + tid];
    }
    float acc[4][4] = {};

    for (int k0 = 0; k0 < CH; k0 += 32) {
#pragma unroll
        for (int l = 0; l < 2; l++) {
            int idx = tid + l * 256;
            int r = idx >> 3;
            int c = (idx & 7) << 2;
            float4 v = *(const float4*)&F[(size_t)(bn + r) * CH + k0 + c];
            As[r][c] = v.x; As[r][c + 1] = v.y; As[r][c + 2] = v.z; As[r][c + 3] = v.w;
            float4 w = *(const float4*)&F[(size_t)(bj + r) * CH + k0 + c];
            Bs[r][c] = w.x; Bs[r][c + 1] = w.y; Bs[r][c + 2] = w.z; Bs[r][c + 3] = w.w;
        }
        __syncthreads();
#pragma unroll
        for (int kk = 0; kk < 32; kk++) {
            float a[4], b[4];
#pragma unroll
            for (int i = 0; i < 4; i++) a[i] = As[ty * 4 + i][kk];
#pragma unroll
            for (int j = 0; j < 4; j++) b[j] = Bs[tx * 4 + j][kk];
#pragma unroll
            for (int i = 0; i < 4; i++)
#pragma unroll
                for (int j = 0; j < 4; j++) acc[i][j] += a[i] * b[j];
        }
        __syncthreads();
    }
#pragma unroll
    for (int i = 0; i < 4; i++) {
        int rrel = ty * 4 + i;
        int nrow = bn + rrel;
        int lbl = s_lbl[rrel];
        float thr = s_thr[rrel];
#pragma unroll
        for (int j = 0; j < 4; j++) {
            int col = s_col[tx * 4 + j];
            float v = acc[i][j];
            g_pairs[(size_t)nrow * BR + col] = v;
            if (col % 60 == lbl) {
                g_posvals[nrow * MEMSZ + (unsigned)(col - lbl) / 60u] = v;
            } else if (v >= thr) {
                int p = atomicAdd(&g_cntH[nrow], 1);
                if (p < CAPN) g_listH[(size_t)nrow * CAPN + p] = fkey(v);
            }
        }
    }
}

// ------- rand collect: stream rnd only, push candidates ---------------------
__global__ __launch_bounds__(256) void randcol_kernel(const int* __restrict__ label,
                                                      const float* __restrict__ rnd) {
    __shared__ uint32_t s_neg[324];
    const int n = blockIdx.x >> 2;
    const int q = blockIdx.x & 3;
    const int lbl = label[n];
    const float* rrow = rnd + (size_t)n * BR;
    const float tR = g_thrR[n];
    const int tid = threadIdx.x, lane = tid & 31;
    const int base = q * QCOLS;
    const int w0 = base >> 5;
    const int wEnd = (base + QCOLS - 1) >> 5;

    for (int w = w0 + tid; w <= wEnd; w += 256)
        s_neg[w - w0] = g_validbits[w] & ~g_eqtab[lbl * 15 + (w % 15)];
    __syncthreads();

    for (int g = tid; g < QGPAD; g += 256) {
        uint32_t nm = 0;
        const int j0 = base + g * 4;
        float rr[4] = {0, 0, 0, 0};
        if (g < QGROUPS) {
            int w = j0 >> 5, sh = j0 & 31;
            nm = (s_neg[w - w0] >> sh) & 0xF;
            float4 r4 = *(const float4*)(rrow + j0);
            rr[0] = r4.x; rr[1] = r4.y; rr[2] = r4.z; rr[3] = r4.w;
        }
        uint32_t rF = 0;
#pragma unroll
        for (int e = 0; e < 4; e++)
            if (((nm >> e) & 1) && rr[e] <= tR) rF |= 1u << e;
        int nR = __popc(rF);
        if (__any_sync(0xffffffffu, nR)) {
            int inc = warpIncScan(nR);
            int tot = __shfl_sync(0xffffffffu, inc, 31);
            int baseR = 0;
            if (lane == 31 && tot) baseR = atomicAdd(&g_cntR[n], tot);
            baseR = __shfl_sync(0xffffffffu, baseR, 31);
            int offR = baseR + inc - nR;
            if (rF) {
#pragma unroll
                for (int e = 0; e < 4; e++)
                    if (rF & (1u << e)) {
                        if (offR < CAPN)
                            g_listR[(size_t)n * CAPN + offR] =
                                ((u64)__float_as_uint(rr[e]) << 32) | (unsigned)(j0 + e);
                        offR++;
                    }
            }
        }
    }
}

// ------------------------- select + loss ------------------------------------
__device__ __forceinline__ int blockReduceInt(int c, int* s_red) {
    __syncthreads();
    if (threadIdx.x == 0) *s_red = 0;
    __syncthreads();
    c = warpRedInt(c);
    if ((threadIdx.x & 31) == 0) atomicAdd(s_red, c);
    __syncthreads();
    return *s_red;
}
__device__ __forceinline__ float blockReduceFloat(float v, float* warpBuf) {
    v = warpRedF(v);
    int lane = threadIdx.x & 31, w = threadIdx.x >> 5;
    if (lane == 0) warpBuf[w] = v;
    __syncthreads();
    float s = 0.f;
    if (threadIdx.x == 0)
        for (int i = 0; i < (int)(blockDim.x >> 5); i++) s += warpBuf[i];
    __syncthreads();
    return s;
}
__device__ __forceinline__ double blockReduceDouble(double v, double* warpBuf) {
#pragma unroll
    for (int o = 16; o > 0; o >>= 1) v += __shfl_xor_sync(0xffffffffu, v, o);
    int lane = threadIdx.x & 31, w = threadIdx.x >> 5;
    if (lane == 0) warpBuf[w] = v;
    __syncthreads();
    double s = 0.0;
    if (threadIdx.x == 0)
        for (int i = 0; i < (int)(blockDim.x >> 5); i++) s += warpBuf[i];
    __syncthreads();
    return s;
}
__device__ __forceinline__ double lterm(float pv, float Eh, float Er) {
    float e = expf(pv);
    return (double)(logf(e + Eh) - pv) + (double)(logf(e + Er) - pv);
}

__device__ uint32_t warp_sel_largest_u32(const uint32_t* a, int len, int need) {
    int lane = threadIdx.x & 31;
    uint32_t lo = 0, hi = 0xFFFFFFFFu;
    while (lo < hi) {
        uint32_t d = hi - lo;
        uint32_t mid = lo + (d >> 1) + (d & 1);
        int c = 0;
        for (int i = lane; i < len; i += 32) c += (a[i] >= mid);
        c = warpRedInt(c);
        if (c >= need) lo = mid; else hi = mid - 1;
    }
    return lo;
}
__device__ uint32_t warp_sel_smallest_fkey(const float* a, int len, int need) {
    int lane = threadIdx.x & 31;
    uint32_t lo = 0, hi = 0xFFFFFFFFu;
    while (lo < hi) {
        uint32_t mid = lo + ((hi - lo) >> 1);
        int c = 0;
        for (int i = lane; i < len; i += 32) c += (fkey(a[i]) <= mid);
        c = warpRedInt(c);
        if (c >= need) hi = mid; else lo = mid + 1;
    }
    return lo;
}

__global__ __launch_bounds__(128) void select_kernel(const int* __restrict__ label,
                                                     const float* __restrict__ rnd) {
    __shared__ uint32_t s_listH[CAPN];
    __shared__ u64      s_listR[CAPN];
    __shared__ float    s_pos[MEMSZ];
    __shared__ float    s_warp[4];
    __shared__ double   s_warpd[4];
    __shared__ int      s_red;
    __shared__ uint32_t s_thrP;
    __shared__ float    s_Eh, s_Er;

    const int n = blockIdx.x;
    const int lbl = label[n];
    const float* row  = g_pairs + (size_t)n * BR;
    const float* rrow = rnd + (size_t)n * BR;
    const int tid = threadIdx.x, wid = tid >> 5, lane = tid & 31;

    const int rawH = g_cntH[n], rawR = g_cntR[n];
    const bool okH = (rawH >= NEGN && rawH <= CAPN);
    const bool okR = (rawR >= NEGN && rawR <= CAPN);
    if (okH) for (int i = tid; i < rawH; i += 128) s_listH[i] = g_listH[(size_t)n * CAPN + i];
    if (okR) for (int i = tid; i < rawR; i += 128) s_listR[i] = g_listR[(size_t)n * CAPN + i];
    for (int i = tid; i < MEMSZ; i += 128) s_pos[i] = g_posvals[n * MEMSZ + i];
    __syncthreads();

    if (okH && wid == 0) {
        uint32_t t = warp_sel_largest_u32(s_listH, rawH, NEGN);
        int cg = 0; float se = 0.f;
        for (int i = lane; i < rawH; i += 32) {
            uint32_t u = s_listH[i];
            if (u > t) { cg++; se += expf(unfkey(u)); }
        }
        cg = warpRedInt(cg); se = warpRedF(se);
        if (lane == 0) s_Eh = se + (float)(NEGN - cg) * expf(unfkey(t));
    }
    if (okR && wid == 1) {
        uint32_t lo = 0, hi = 0xFFFFFFFFu;
        while (lo < hi) {
            uint32_t mid = lo + ((hi - lo) >> 1);
            int c = 0;
            for (int i = lane; i < rawR; i += 32)
                c += ((uint32_t)(s_listR[i] >> 32) <= mid);
            c = warpRedInt(c);
            if (c >= NEGN) hi = mid; else lo = mid + 1;
        }
        const uint32_t kv = lo;
        int cl = 0, ce = 0;
        for (int i = lane; i < rawR; i += 32) {
            uint32_t k = (uint32_t)(s_listR[i] >> 32);
            cl += (k < kv); ce += (k == kv);
        }
        cl = warpRedInt(cl); ce = warpRedInt(ce);
        const int need2 = NEGN - cl;
        uint32_t ti = 0xFFFFFFFFu;
        if (ce != need2) {
            uint32_t l2 = 0, h2 = 0xFFFFFFFFu;
            while (l2 < h2) {
                uint32_t mid = l2 + ((h2 - l2) >> 1);
                int c = 0;
                for (int i = lane; i < rawR; i += 32) {
                    u64 w = s_listR[i];
                    c += (((uint32_t)(w >> 32) == kv) && ((uint32_t)w <= mid));
                }
                c = warpRedInt(c);
                if (c >= need2) h2 = mid; else l2 = mid + 1;
            }
            ti = l2;
        }
        float se = 0.f;
        for (int i = lane; i < rawR; i += 32) {
            u64 w = s_listR[i];
            uint32_t k = (uint32_t)(w >> 32);
            if (k < kv || (k == kv && (uint32_t)w <= ti))
                se += expf(row[(uint32_t)w]);
        }
        se = warpRedF(se);
        if (lane == 0) s_Er = se;
    }
    if (wid == 2) {
        uint32_t t = warp_sel_smallest_fkey(s_pos, MEMSZ, POSN);
        if (lane == 0) s_thrP = t;
    }
    __syncthreads();

    // ---- rare fallbacks: block-wide bisect over gmem ------------------------
    if (!okH) {
        uint32_t lo = 0, hi = 0xFFFFFFFFu;
        while (lo < hi) {
            uint32_t d = hi - lo;
            uint32_t mid = lo + (d >> 1) + (d & 1);
            int c = 0;
            for (int j = tid; j < BR; j += 128) {
                int w = j >> 5;
                if (((g_validbits[w] & ~g_eqtab[lbl * 15 + (w % 15)]) >> (j & 31)) & 1)
                    c += (fkey(row[j]) >= mid);
            }
            c = blockReduceInt(c, &s_red);
            if (c >= NEGN) lo = mid; else hi = mid - 1;
        }
        uint32_t t = lo;
        int cg = 0; float se = 0.f;
        for (int j = tid; j < BR; j += 128) {
            int w = j >> 5;
            if (((g_validbits[w] & ~g_eqtab[lbl * 15 + (w % 15)]) >> (j & 31)) & 1) {
                float x = row[j];
                if (fkey(x) > t) { cg++; se += expf(x); }
            }
        }
        cg = blockReduceInt(cg, &s_red);
        float tot = blockReduceFloat(se, s_warp);
        if (tid == 0) s_Eh = tot + (float)(NEGN - cg) * expf(unfkey(t));
        __syncthreads();
    }
    if (!okR) {
        u64 lo = 0ull, hi = 0xFFFFFFFFFFFFFFFFull;
        while (lo < hi) {
            u64 mid = lo + ((hi - lo) >> 1);
            int c = 0;
            for (int j = tid; j < BR; j += 128) {
                int w = j >> 5;
                if (((g_validbits[w] & ~g_eqtab[lbl * 15 + (w % 15)]) >> (j & 31)) & 1) {
                    u64 wv = ((u64)__float_as_uint(rrow[j]) << 32) | (unsigned)j;
                    c += (wv <= mid);
                }
            }
            c = blockReduceInt(c, &s_red);
            if (c >= NEGN) hi = mid; else lo = mid + 1;
        }
        const u64 t = lo;
        float se = 0.f;
        for (int j = tid; j < BR; j += 128) {
            int w = j >> 5;
            if (((g_validbits[w] & ~g_eqtab[lbl * 15 + (w % 15)]) >> (j & 31)) & 1) {
                u64 wv = ((u64)__float_as_uint(rrow[j]) << 32) | (unsigned)j;
                if (wv <= t) se += expf(row[j]);
            }
        }
        float tot = blockReduceFloat(se, s_warp);
        if (tid == 0) s_Er = tot;
        __syncthreads();
    }

    // ---- per-row loss: 128 smallest pos values (with ties) ------------------
    const float Eh = s_Eh, Er = s_Er;
    const uint32_t tP = s_thrP;
    int c = 0; double ts = 0.0;
    for (int i = tid; i < MEMSZ; i += 128) {
        float pv = s_pos[i];
        if (fkey(pv) < tP) { c++; ts += lterm(pv, Eh, Er); }
    }
    c = blockReduceInt(c, &s_red);
    double tsum = blockReduceDouble(ts, s_warpd);
    if (tid == 0) {
        tsum += (double)(POSN - c) * lterm(unfkey(tP), Eh, Er);
        atomicAdd(&g_loss, tsum);
    }
}

__global__ void finalize_kernel(float* out) {
    out[0] = (float)(g_loss / (double)(BATCH * 2 * POSN));
}

// ------------------------- launcher -----------------------------------------
extern "C" void kernel_launch(void* const* d_in, const int* in_sizes, int n_in,
                              void* d_out, int out_size) {
    const float* f    = (const float*)d_in[0];
    const int*   lab  = (const int*)d_in[1];
    const int*   eidx = (const int*)d_in[2];
    const float* bank = (const float*)d_in[3];
    const float* flag = (const float*)d_in[4];
    const float* rnd  = (const float*)d_in[5];
    float* out = (float*)d_out;

    const int GEMM_SMEM = 2 * 2 * GBM * GPAD * 4;   // 73728 bytes
    cudaFuncSetAttribute(gemm_tf32_kernel,
                         cudaFuncAttributeMaxDynamicSharedMemorySize, GEMM_SMEM);

    prep_kernel<<<(BATCH * MEMSZ + 255) / 256, 256>>>(flag);
    scatter_kernel<<<2, 256>>>(eidx);
    samp_gemm_kernel<<<dim3(SAMPN / 64, BATCH / 64), 256>>>(f, bank);
    thresh_kernel<<<BATCH / 8, 256>>>(lab, rnd);
    gemm_tf32_kernel<<<dim3((BR + GBN - 1) / GBN, BATCH / GBM), 128, GEMM_SMEM>>>(f, bank, lab);
    fixup_gemm_kernel<<<dim3(BATCH / 64, BATCH / 64), 256>>>(f, eidx, lab);
    randcol_kernel<<<4 * BATCH, 256>>>(lab, rnd);
    select_kernel<<<BATCH, 128>>>(lab, rnd);
    finalize_kernel<<<1, 1>>>(out);
    (void)in_sizes; (void)n_in; (void)out_size;
}

// round 12
// speedup vs baseline: 1.3429x; 1.3429x over previous
#include <cuda_runtime.h>
#include <math.h>
#include <stdint.h>

#define BATCH 512
#define CH    256
#define CLS   60
#define MEMSZ 684
#define BR    41040
#define POSN  128
#define NEGN  512
#define NWORDS 1283          // ceil(BR/32)
#define CAPN  2048
#define NQ    (BR/4)         // 10260 float4 per row
#define NITER 21             // ceil(NQ/512)

typedef unsigned long long u64;

// ------------------------- device scratch -----------------------------------
__device__ float    g_pairs[(size_t)BATCH * BR];   // 84 MB
__device__ uint32_t g_validbits[NWORDS];
__device__ uint32_t g_eqtab[CLS * 15];
__device__ double   g_loss;

// ------------------------- prep ---------------------------------------------
__global__ void prep_kernel(const float* __restrict__ flag) {
    int i = blockIdx.x * blockDim.x + threadIdx.x;
    if (i == 0) g_loss = 0.0;
    if (i < CLS * 15) {
        int lbl = i / 15, p = i % 15;
        int off = (32 * p) % 60;
        uint32_t m = 0;
        for (int b = 0; b < 32; b++) if ((off + b) % 60 == lbl) m |= 1u << b;
        g_eqtab[i] = m;
    }
    if (i < NWORDS) {
        uint32_t m = 0; int base = i * 32;
        for (int b = 0; b < 32; b++) {
            int j = base + b;
            if (j < BR && flag[j] > 0.f) m |= 1u << b;
        }
        g_validbits[i] = m;
    }
}

__global__ void scatter_kernel(const int* __restrict__ eidx) {
    int m = blockIdx.x * blockDim.x + threadIdx.x;
    if (m < BATCH) { int j = eidx[m]; atomicOr(&g_validbits[j >> 5], 1u << (j & 31)); }
}

// ------------------------- tf32 tensor-core GEMM (proven 128x128) -----------
#define GBM 128
#define GBN 128
#define GBK 32
#define GPAD 36
#define GKITERS 8

__device__ __forceinline__ void mma_tf32(float* c, const uint32_t* a, const uint32_t* b) {
    asm volatile(
        "mma.sync.aligned.m16n8k8.row.col.f32.tf32.tf32.f32 "
        "{%0,%1,%2,%3},{%4,%5,%6,%7},{%8,%9},{%0,%1,%2,%3};"
        : "+f"(c[0]), "+f"(c[1]), "+f"(c[2]), "+f"(c[3])
        : "r"(a[0]), "r"(a[1]), "r"(a[2]), "r"(a[3]), "r"(b[0]), "r"(b[1]));
}

__global__ __launch_bounds__(128) void gemm_tf32_kernel(const float* __restrict__ F,
                                                        const float* __restrict__ BK_) {
    extern __shared__ float sm[];
    float* As = sm;
    float* Bs = sm + 2 * GBM * GPAD;
#define ASM(bf, r, c) As[(bf) * GBM * GPAD + (r) * GPAD + (c)]
#define BSM(bf, r, c) Bs[(bf) * GBM * GPAD + (r) * GPAD + (c)]

    const int bj = blockIdx.x * GBN;
    const int bn = blockIdx.y * GBM;
    const int tid = threadIdx.x;
    const int wid = tid >> 5, lane = tid & 31;
    const int wm = (wid >> 1) * 64, wn = (wid & 1) * 64;
    const int tr = lane >> 2, tc = lane & 3;

    float acc[4][8][4];
#pragma unroll
    for (int i = 0; i < 4; i++)
#pragma unroll
        for (int j = 0; j < 8; j++)
#pragma unroll
            for (int k = 0; k < 4; k++) acc[i][j][k] = 0.f;

    auto load_stage = [&](int buf, int kt) {
        int k0 = kt * GBK;
#pragma unroll
        for (int i = 0; i < 8; i++) {
            int slot = tid + i * 128;
            int r = slot >> 3;
            int kq = (slot & 7) * 4;
            uint32_t da = (uint32_t)__cvta_generic_to_shared(&ASM(buf, r, kq));
            const float* ga = F + (size_t)(bn + r) * CH + k0 + kq;
            asm volatile("cp.async.cg.shared.global [%0], [%1], 16;" :: "r"(da), "l"(ga));
            int j = bj + r;
            int ok = (j < BR) ? 16 : 0;
            const float* gb = BK_ + (size_t)(j < BR ? j : 0) * CH + k0 + kq;
            uint32_t db = (uint32_t)__cvta_generic_to_shared(&BSM(buf, r, kq));
            asm volatile("cp.async.cg.shared.global [%0], [%1], 16, %2;" :: "r"(db), "l"(gb), "r"(ok));
        }
    };

    load_stage(0, 0);
    asm volatile("cp.async.commit_group;");

    for (int kt = 0; kt < GKITERS; kt++) {
        asm volatile("cp.async.wait_group 0;");
        __syncthreads();
        if (kt + 1 < GKITERS) {
            load_stage((kt + 1) & 1, kt + 1);
            asm volatile("cp.async.commit_group;");
        }
        int b = kt & 1;
#pragma unroll
        for (int ks = 0; ks < 4; ks++) {
            int kk = ks * 8;
            uint32_t af[4][4], bf[8][2];
#pragma unroll
            for (int mi = 0; mi < 4; mi++) {
                int r0 = wm + mi * 16 + tr;
                af[mi][0] = __float_as_uint(ASM(b, r0,     kk + tc));
                af[mi][1] = __float_as_uint(ASM(b, r0 + 8, kk + tc));
                af[mi][2] = __float_as_uint(ASM(b, r0,     kk + tc + 4));
                af[mi][3] = __float_as_uint(ASM(b, r0 + 8, kk + tc + 4));
            }
#pragma unroll
            for (int ni = 0; ni < 8; ni++) {
                int r0 = wn + ni * 8 + tr;
                bf[ni][0] = __float_as_uint(BSM(b, r0, kk + tc));
                bf[ni][1] = __float_as_uint(BSM(b, r0, kk + tc + 4));
            }
#pragma unroll
            for (int mi = 0; mi < 4; mi++)
#pragma unroll
                for (int ni = 0; ni < 8; ni++) mma_tf32(acc[mi][ni], af[mi], bf[ni]);
        }
    }

#pragma unroll
    for (int mi = 0; mi < 4; mi++) {
        int m = bn + wm + mi * 16 + tr;
        float* p0 = &g_pairs[(size_t)m * BR];
        float* p1 = &g_pairs[(size_t)(m + 8) * BR];
#pragma unroll
        for (int ni = 0; ni < 8; ni++) {
            int col = bj + wn + ni * 8 + tc * 2;
            if (col < BR) {
                *(float2*)(p0 + col) = make_float2(acc[mi][ni][0], acc[mi][ni][1]);
                *(float2*)(p1 + col) = make_float2(acc[mi][ni][2], acc[mi][ni][3]);
            }
        }
    }
#undef ASM
#undef BSM
}

// -------- fixup: S = F @ F^T (fp32, tiled), scatter to enqueued columns -----
__global__ __launch_bounds__(256) void fixup_gemm_kernel(const float* __restrict__ F,
                                                         const int* __restrict__ eidx) {
    __shared__ float As[64][33];
    __shared__ float Bs[64][33];
    __shared__ int   s_col[64];
    const int bj = blockIdx.x * 64;
    const int bn = blockIdx.y * 64;
    const int tid = threadIdx.x;
    const int tx = tid & 15, ty = tid >> 4;
    if (tid < 64) s_col[tid] = eidx[bj + tid];
    float acc[4][4] = {};

    for (int k0 = 0; k0 < CH; k0 += 32) {
#pragma unroll
        for (int l = 0; l < 2; l++) {
            int idx = tid + l * 256;
            int r = idx >> 3;
            int c = (idx & 7) << 2;
            float4 v = *(const float4*)&F[(size_t)(bn + r) * CH + k0 + c];
            As[r][c] = v.x; As[r][c + 1] = v.y; As[r][c + 2] = v.z; As[r][c + 3] = v.w;
            float4 w = *(const float4*)&F[(size_t)(bj + r) * CH + k0 + c];
            Bs[r][c] = w.x; Bs[r][c + 1] = w.y; Bs[r][c + 2] = w.z; Bs[r][c + 3] = w.w;
        }
        __syncthreads();
#pragma unroll
        for (int kk = 0; kk < 32; kk++) {
            float a[4], b[4];
#pragma unroll
            for (int i = 0; i < 4; i++) a[i] = As[ty * 4 + i][kk];
#pragma unroll
            for (int j = 0; j < 4; j++) b[j] = Bs[tx * 4 + j][kk];
#pragma unroll
            for (int i = 0; i < 4; i++)
#pragma unroll
                for (int j = 0; j < 4; j++) acc[i][j] += a[i] * b[j];
        }
        __syncthreads();
    }
#pragma unroll
    for (int i = 0; i < 4; i++) {
        int nrow = bn + ty * 4 + i;
#pragma unroll
        for (int j = 0; j < 4; j++)
            g_pairs[(size_t)nrow * BR + s_col[tx * 4 + j]] = acc[i][j];
    }
}

// ------------------------- helpers ------------------------------------------
__device__ __forceinline__ uint32_t fkey(float v) {
    uint32_t u = __float_as_uint(v);
    return (u & 0x80000000u) ? ~u : (u | 0x80000000u);
}
__device__ __forceinline__ float unfkey(uint32_t u) {
    uint32_t b = (u & 0x80000000u) ? (u & 0x7FFFFFFFu) : ~u;
    return __uint_as_float(b);
}

__device__ __forceinline__ int warpRedInt(int c) {
#pragma unroll
    for (int o = 16; o > 0; o >>= 1) c += __shfl_xor_sync(0xffffffffu, c, o);
    return c;
}
__device__ __forceinline__ float warpRedF(float v) {
#pragma unroll
    for (int o = 16; o > 0; o >>= 1) v += __shfl_xor_sync(0xffffffffu, v, o);
    return v;
}

__device__ uint32_t warp_sel_largest_u32(const uint32_t* a, int len, int need) {
    int lane = threadIdx.x & 31;
    uint32_t lo = 0, hi = 0xFFFFFFFFu;
    while (lo < hi) {
        uint32_t d = hi - lo;
        uint32_t mid = lo + (d >> 1) + (d & 1);
        int c = 0;
        for (int i = lane; i < len; i += 32) c += (a[i] >= mid);
        c = warpRedInt(c);
        if (c >= need) lo = mid; else hi = mid - 1;
    }
    return lo;
}
__device__ uint32_t warp_sel_smallest_u32(const uint32_t* a, int len, int need) {
    int lane = threadIdx.x & 31;
    uint32_t lo = 0, hi = 0xFFFFFFFFu;
    while (lo < hi) {
        uint32_t mid = lo + ((hi - lo) >> 1);
        int c = 0;
        for (int i = lane; i < len; i += 32) c += (a[i] <= mid);
        c = warpRedInt(c);
        if (c >= need) hi = mid; else lo = mid + 1;
    }
    return lo;
}
__device__ u64 warp_sel_smallest_u64(const u64* a, int len, int need) {
    int lane = threadIdx.x & 31;
    u64 lo = 0ull, hi = 0xFFFFFFFFFFFFFFFFull;
    while (lo < hi) {
        u64 mid = lo + ((hi - lo) >> 1);
        int c = 0;
        for (int i = lane; i < len; i += 32) c += (a[i] <= mid);
        c = warpRedInt(c);
        if (c >= need) hi = mid; else lo = mid + 1;
    }
    return lo;
}
__device__ uint32_t warp_sel_smallest_fkey(const float* a, int len, int need) {
    int lane = threadIdx.x & 31;
    uint32_t lo = 0, hi = 0xFFFFFFFFu;
    while (lo < hi) {
        uint32_t mid = lo + ((hi - lo) >> 1);
        int c = 0;
        for (int i = lane; i < len; i += 32) c += (fkey(a[i]) <= mid);
        c = warpRedInt(c);
        if (c >= need) hi = mid; else lo = mid + 1;
    }
    return lo;
}

__device__ __forceinline__ int blockReduceInt(int c, int* s_red) {
    __syncthreads();
    if (threadIdx.x == 0) *s_red = 0;
    __syncthreads();
    c = warpRedInt(c);
    if ((threadIdx.x & 31) == 0) atomicAdd(s_red, c);
    __syncthreads();
    return *s_red;
}
__device__ __forceinline__ float blockReduceFloat(float v, float* warpBuf) {
    v = warpRedF(v);
    int lane = threadIdx.x & 31, w = threadIdx.x >> 5;
    if (lane == 0) warpBuf[w] = v;
    __syncthreads();
    float s = 0.f;
    if (threadIdx.x == 0)
        for (int i = 0; i < (int)(blockDim.x >> 5); i++) s += warpBuf[i];
    __syncthreads();
    return s;   // thread 0 only
}
__device__ __forceinline__ double blockReduceDouble(double v, double* warpBuf) {
#pragma unroll
    for (int o = 16; o > 0; o >>= 1) v += __shfl_xor_sync(0xffffffffu, v, o);
    int lane = threadIdx.x & 31, w = threadIdx.x >> 5;
    if (lane == 0) warpBuf[w] = v;
    __syncthreads();
    double s = 0.0;
    if (threadIdx.x == 0)
        for (int i = 0; i < (int)(blockDim.x >> 5); i++) s += warpBuf[i];
    __syncthreads();
    return s;   // thread 0 only
}

__device__ __forceinline__ double lterm(float pv, float Eh, float Er) {
    float e = expf(pv);
    return (double)(logf(e + Eh) - pv) + (double)(logf(e + Er) - pv);
}

// ------- fused: hard top-512 + rand 512 + pos-128 + per-row loss ------------
__global__ __launch_bounds__(512) void negsel_kernel(const int* __restrict__ label,
                                                     const float* __restrict__ rnd) {
    __shared__ uint32_t s_negmask[NWORDS];
    __shared__ uint32_t s_posmask[NWORDS];
    __shared__ uint32_t s_listH[CAPN];
    __shared__ u64      s_listR[CAPN];
    __shared__ uint32_t s_samp[1024];
    __shared__ float    s_pos[MEMSZ];
    __shared__ int      s_cntH, s_cntR, s_red;
    __shared__ float    s_warp[16];
    __shared__ double   s_warpd[16];
    __shared__ uint32_t s_thrH, s_thrP, s_thrRs;
    __shared__ u64      s_thrR;
    __shared__ float    s_Eh, s_Er;

    const int n = blockIdx.x;
    const int lbl = label[n];
    const float* row  = g_pairs + (size_t)n * BR;
    const float* rrow = rnd + (size_t)n * BR;
    const int tid = threadIdx.x, wid = tid >> 5, lane = tid & 31;

    for (int w = tid; w < NWORDS; w += 512) {
        uint32_t v = g_validbits[w], e = g_eqtab[lbl * 15 + (w % 15)];
        s_negmask[w] = v & ~e;
        s_posmask[w] = v & e;
    }
    for (int i = tid; i < MEMSZ; i += 512) s_pos[i] = INFINITY;
    if (tid == 0) { s_cntH = 0; s_cntR = 0; }
    __syncthreads();

    // ---- sampled thresholds -------------------------------------------------
    for (int s = tid; s < 1024; s += 512) {
        int j = 37 * s + 11;
        bool ok = (s_negmask[j >> 5] >> (j & 31)) & 1;
        s_samp[s] = ok ? fkey(row[j]) : 0u;
    }
    __syncthreads();
    if (wid == 0) { uint32_t t = warp_sel_largest_u32(s_samp, 1024, 32);
                    if (lane == 0) s_thrH = t; }
    __syncthreads();
    for (int s = tid; s < 1024; s += 512) {
        int j = 37 * s + 11;
        bool ok = (s_negmask[j >> 5] >> (j & 31)) & 1;
        s_samp[s] = ok ? __float_as_uint(rrow[j]) : 0xFFFFFFFFu;
    }
    __syncthreads();
    if (wid == 1) { uint32_t t = warp_sel_smallest_u32(s_samp, 1024, 32);
                    if (lane == 0) s_thrRs = t; }
    __syncthreads();
    const float thrHs = unfkey(s_thrH);
    const float thrRs = __uint_as_float(s_thrRs);

    // ---- fused scan: 3-deep load batching for MLP ---------------------------
    for (int it = 0; it < NITER; it += 3) {
        int   q[3];
        uint32_t nm[3], pm[3];
        float vv[3][4], rr[3][4];
#pragma unroll
        for (int b = 0; b < 3; b++) {
            q[b] = (it + b) * 512 + tid;
            bool live = (q[b] < NQ);
            nm[b] = 0; pm[b] = 0;
            if (live) {
                uint32_t mw = s_negmask[q[b] >> 3], pw = s_posmask[q[b] >> 3];
                int sh = (q[b] & 7) << 2;
                nm[b] = (mw >> sh) & 0xF;
                pm[b] = (pw >> sh) & 0xF;
                float4 v4 = ((const float4*)row)[q[b]];
                vv[b][0] = v4.x; vv[b][1] = v4.y; vv[b][2] = v4.z; vv[b][3] = v4.w;
                float4 r4 = ((const float4*)rrow)[q[b]];
                rr[b][0] = r4.x; rr[b][1] = r4.y; rr[b][2] = r4.z; rr[b][3] = r4.w;
            }
        }
#pragma unroll
        for (int b = 0; b < 3; b++) {
            if (!(nm[b] | pm[b])) continue;
            const int j0 = q[b] << 2;
            if (pm[b]) {
#pragma unroll
                for (int e = 0; e < 4; e++)
                    if ((pm[b] >> e) & 1)
                        s_pos[(unsigned)(j0 + e - lbl) / 60u] = vv[b][e];
            }
            if (nm[b]) {
#pragma unroll
                for (int e = 0; e < 4; e++) {
                    if ((nm[b] >> e) & 1) {
                        if (vv[b][e] >= thrHs) {
                            int p = atomicAdd(&s_cntH, 1);
                            if (p < CAPN) s_listH[p] = fkey(vv[b][e]);
                        }
                        if (rr[b][e] <= thrRs) {
                            int p = atomicAdd(&s_cntR, 1);
                            if (p < CAPN)
                                s_listR[p] = ((u64)__float_as_uint(rr[b][e]) << 32) |
                                             (unsigned)(j0 + e);
                        }
                    }
                }
            }
        }
    }
    __syncthreads();
    const int cntH = s_cntH, cntR = s_cntR;
    const bool okH = (cntH >= NEGN && cntH <= CAPN);
    const bool okR = (cntR >= NEGN && cntR <= CAPN);

    // ---- thresholds: warps 0/1/2 in parallel (shfl-only) --------------------
    if (okH && wid == 0) { uint32_t t = warp_sel_largest_u32(s_listH, cntH, NEGN);
                           if (lane == 0) s_thrH = t; }
    if (okR && wid == 1) { u64 t = warp_sel_smallest_u64(s_listR, cntR, NEGN);
                           if (lane == 0) s_thrR = t; }
    if (wid == 2) { uint32_t t = warp_sel_smallest_fkey(s_pos, MEMSZ, POSN);
                    if (lane == 0) s_thrP = t; }
    __syncthreads();

    // ---- rare fallbacks: block-wide bisect over gmem ------------------------
    if (!okH) {
        uint32_t lo = 0, hi = 0xFFFFFFFFu;
        while (lo < hi) {
            uint32_t d = hi - lo;
            uint32_t mid = lo + (d >> 1) + (d & 1);
            int c = 0;
            for (int j = tid; j < BR; j += 512)
                if ((s_negmask[j >> 5] >> (j & 31)) & 1) c += (fkey(row[j]) >= mid);
            c = blockReduceInt(c, &s_red);
            if (c >= NEGN) lo = mid; else hi = mid - 1;
        }
        if (tid == 0) s_thrH = lo;
        __syncthreads();
    }
    if (!okR) {
        u64 lo = 0ull, hi = 0xFFFFFFFFFFFFFFFFull;
        while (lo < hi) {
            u64 mid = lo + ((hi - lo) >> 1);
            int c = 0;
            for (int j = tid; j < BR; j += 512)
                if ((s_negmask[j >> 5] >> (j & 31)) & 1) {
                    u64 w = ((u64)__float_as_uint(rrow[j]) << 32) | (unsigned)j;
                    c += (w <= mid);
                }
            c = blockReduceInt(c, &s_red);
            if (c >= NEGN) hi = mid; else lo = mid + 1;
        }
        if (tid == 0) s_thrR = lo;
        __syncthreads();
    }

    // ---- Eh / Er sums -------------------------------------------------------
    if (okH && wid == 0) {
        uint32_t t = s_thrH;
        int cg = 0; float se = 0.f;
        for (int i = lane; i < cntH; i += 32) {
            uint32_t u = s_listH[i];
            if (u > t) { cg++; se += expf(unfkey(u)); }
        }
        cg = warpRedInt(cg); se = warpRedF(se);
        if (lane == 0) s_Eh = se + (float)(NEGN - cg) * expf(unfkey(t));
    }
    if (okR && wid == 1) {
        u64 t = s_thrR;
        float se = 0.f;
        for (int i = lane; i < cntR; i += 32) {
            u64 w = s_listR[i];
            if (w <= t) se += expf(row[(unsigned)(w & 0xFFFFFFFFull)]);
        }
        se = warpRedF(se);
        if (lane == 0) s_Er = se;
    }
    __syncthreads();
    if (!okH) {
        uint32_t t = s_thrH;
        int cg = 0; float se = 0.f;
        for (int j = tid; j < BR; j += 512)
            if ((s_negmask[j >> 5] >> (j & 31)) & 1) {
                float x = row[j];
                if (fkey(x) > t) { cg++; se += expf(x); }
            }
        cg = blockReduceInt(cg, &s_red);
        float tot = blockReduceFloat(se, s_warp);
        if (tid == 0) s_Eh = tot + (float)(NEGN - cg) * expf(unfkey(t));
        __syncthreads();
    }
    if (!okR) {
        u64 t = s_thrR;
        float se = 0.f;
        for (int j = tid; j < BR; j += 512)
            if ((s_negmask[j >> 5] >> (j & 31)) & 1) {
                u64 w = ((u64)__float_as_uint(rrow[j]) << 32) | (unsigned)j;
                if (w <= t) se += expf(row[j]);
            }
        float tot = blockReduceFloat(se, s_warp);
        if (tid == 0) s_Er = tot;
        __syncthreads();
    }

    // ---- per-row loss: 128 smallest pos values (with ties) ------------------
    const float Eh = s_Eh, Er = s_Er;
    const uint32_t tP = s_thrP;
    int c = 0; double ts = 0.0;
    for (int i = tid; i < MEMSZ; i += 512) {
        float pv = s_pos[i];
        if (fkey(pv) < tP) { c++; ts += lterm(pv, Eh, Er); }
    }
    c = blockReduceInt(c, &s_red);
    double tsum = blockReduceDouble(ts, s_warpd);
    if (tid == 0) {
        tsum += (double)(POSN - c) * lterm(unfkey(tP), Eh, Er);
        atomicAdd(&g_loss, tsum);
    }
}

__global__ void finalize_kernel(float* out) {
    out[0] = (float)(g_loss / (double)(BATCH * 2 * POSN));
}

// ------------------------- launcher -----------------------------------------
extern "C" void kernel_launch(void* const* d_in, const int* in_sizes, int n_in,
                              void* d_out, int out_size) {
    const float* f    = (const float*)d_in[0];
    const int*   lab  = (const int*)d_in[1];
    const int*   eidx = (const int*)d_in[2];
    const float* bank = (const float*)d_in[3];
    const float* flag = (const float*)d_in[4];
    const float* rnd  = (const float*)d_in[5];
    float* out = (float*)d_out;

    const int GEMM_SMEM = 2 * 2 * GBM * GPAD * 4;   // 73728 bytes
    cudaFuncSetAttribute(gemm_tf32_kernel,
                         cudaFuncAttributeMaxDynamicSharedMemorySize, GEMM_SMEM);

    prep_kernel<<<6, 256>>>(flag);
    scatter_kernel<<<2, 256>>>(eidx);
    gemm_tf32_kernel<<<dim3((BR + GBN - 1) / GBN, BATCH / GBM), 128, GEMM_SMEM>>>(f, bank);
    fixup_gemm_kernel<<<dim3(BATCH / 64, BATCH / 64), 256>>>(f, eidx);
    negsel_kernel<<<BATCH, 512>>>(lab, rnd);
    finalize_kernel<<<1, 1>>>(out);
    (void)in_sizes; (void)n_in; (void)out_size;
}

// round 13
// speedup vs baseline: 1.9013x; 1.4159x over previous
#include <cuda_runtime.h>
#include <math.h>
#include <stdint.h>

#define BATCH 512
#define CH    256
#define CLS   60
#define MEMSZ 684
#define BR    41040
#define POSN  128
#define NEGN  512
#define NWORDS 1283          // ceil(BR/32)
#define CAPN  2048
#define NQ    (BR/4)         // 10260 float4 per row

typedef unsigned long long u64;

// ------------------------- device scratch -----------------------------------
__device__ float    g_pairs[(size_t)BATCH * BR];   // 84 MB
__device__ uint32_t g_validbits[NWORDS];
__device__ uint32_t g_eqtab[CLS * 15];
__device__ double   g_loss;

// ------------------------- prep ---------------------------------------------
__global__ void prep_kernel(const float* __restrict__ flag) {
    int i = blockIdx.x * blockDim.x + threadIdx.x;
    if (i == 0) g_loss = 0.0;
    if (i < CLS * 15) {
        int lbl = i / 15, p = i % 15;
        int off = (32 * p) % 60;
        uint32_t m = 0;
        for (int b = 0; b < 32; b++) if ((off + b) % 60 == lbl) m |= 1u << b;
        g_eqtab[i] = m;
    }
    if (i < NWORDS) {
        uint32_t m = 0; int base = i * 32;
        for (int b = 0; b < 32; b++) {
            int j = base + b;
            if (j < BR && flag[j] > 0.f) m |= 1u << b;
        }
        g_validbits[i] = m;
    }
}

__global__ void scatter_kernel(const int* __restrict__ eidx) {
    int m = blockIdx.x * blockDim.x + threadIdx.x;
    if (m < BATCH) { int j = eidx[m]; atomicOr(&g_validbits[j >> 5], 1u << (j & 31)); }
}

// ------------------------- tf32 tensor-core GEMM (proven 128x128) -----------
#define GBM 128
#define GBN 128
#define GBK 32
#define GPAD 36
#define GKITERS 8

__device__ __forceinline__ void mma_tf32(float* c, const uint32_t* a, const uint32_t* b) {
    asm volatile(
        "mma.sync.aligned.m16n8k8.row.col.f32.tf32.tf32.f32 "
        "{%0,%1,%2,%3},{%4,%5,%6,%7},{%8,%9},{%0,%1,%2,%3};"
        : "+f"(c[0]), "+f"(c[1]), "+f"(c[2]), "+f"(c[3])
        : "r"(a[0]), "r"(a[1]), "r"(a[2]), "r"(a[3]), "r"(b[0]), "r"(b[1]));
}

__global__ __launch_bounds__(128) void gemm_tf32_kernel(const float* __restrict__ F,
                                                        const float* __restrict__ BK_) {
    extern __shared__ float sm[];
    float* As = sm;
    float* Bs = sm + 2 * GBM * GPAD;
#define ASM(bf, r, c) As[(bf) * GBM * GPAD + (r) * GPAD + (c)]
#define BSM(bf, r, c) Bs[(bf) * GBM * GPAD + (r) * GPAD + (c)]

    const int bj = blockIdx.x * GBN;
    const int bn = blockIdx.y * GBM;
    const int tid = threadIdx.x;
    const int wid = tid >> 5, lane = tid & 31;
    const int wm = (wid >> 1) * 64, wn = (wid & 1) * 64;
    const int tr = lane >> 2, tc = lane & 3;

    float acc[4][8][4];
#pragma unroll
    for (int i = 0; i < 4; i++)
#pragma unroll
        for (int j = 0; j < 8; j++)
#pragma unroll
            for (int k = 0; k < 4; k++) acc[i][j][k] = 0.f;

    auto load_stage = [&](int buf, int kt) {
        int k0 = kt * GBK;
#pragma unroll
        for (int i = 0; i < 8; i++) {
            int slot = tid + i * 128;
            int r = slot >> 3;
            int kq = (slot & 7) * 4;
            uint32_t da = (uint32_t)__cvta_generic_to_shared(&ASM(buf, r, kq));
            const float* ga = F + (size_t)(bn + r) * CH + k0 + kq;
            asm volatile("cp.async.cg.shared.global [%0], [%1], 16;" :: "r"(da), "l"(ga));
            int j = bj + r;
            int ok = (j < BR) ? 16 : 0;
            const float* gb = BK_ + (size_t)(j < BR ? j : 0) * CH + k0 + kq;
            uint32_t db = (uint32_t)__cvta_generic_to_shared(&BSM(buf, r, kq));
            asm volatile("cp.async.cg.shared.global [%0], [%1], 16, %2;" :: "r"(db), "l"(gb), "r"(ok));
        }
    };

    load_stage(0, 0);
    asm volatile("cp.async.commit_group;");

    for (int kt = 0; kt < GKITERS; kt++) {
        asm volatile("cp.async.wait_group 0;");
        __syncthreads();
        if (kt + 1 < GKITERS) {
            load_stage((kt + 1) & 1, kt + 1);
            asm volatile("cp.async.commit_group;");
        }
        int b = kt & 1;
#pragma unroll
        for (int ks = 0; ks < 4; ks++) {
            int kk = ks * 8;
            uint32_t af[4][4], bf[8][2];
#pragma unroll
            for (int mi = 0; mi < 4; mi++) {
                int r0 = wm + mi * 16 + tr;
                af[mi][0] = __float_as_uint(ASM(b, r0,     kk + tc));
                af[mi][1] = __float_as_uint(ASM(b, r0 + 8, kk + tc));
                af[mi][2] = __float_as_uint(ASM(b, r0,     kk + tc + 4));
                af[mi][3] = __float_as_uint(ASM(b, r0 + 8, kk + tc + 4));
            }
#pragma unroll
            for (int ni = 0; ni < 8; ni++) {
                int r0 = wn + ni * 8 + tr;
                bf[ni][0] = __float_as_uint(BSM(b, r0, kk + tc));
                bf[ni][1] = __float_as_uint(BSM(b, r0, kk + tc + 4));
            }
#pragma unroll
            for (int mi = 0; mi < 4; mi++)
#pragma unroll
                for (int ni = 0; ni < 8; ni++) mma_tf32(acc[mi][ni], af[mi], bf[ni]);
        }
    }

#pragma unroll
    for (int mi = 0; mi < 4; mi++) {
        int m = bn + wm + mi * 16 + tr;
        float* p0 = &g_pairs[(size_t)m * BR];
        float* p1 = &g_pairs[(size_t)(m + 8) * BR];
#pragma unroll
        for (int ni = 0; ni < 8; ni++) {
            int col = bj + wn + ni * 8 + tc * 2;
            if (col < BR) {
                *(float2*)(p0 + col) = make_float2(acc[mi][ni][0], acc[mi][ni][1]);
                *(float2*)(p1 + col) = make_float2(acc[mi][ni][2], acc[mi][ni][3]);
            }
        }
    }
#undef ASM
#undef BSM
}

// -------- fixup: S = F @ F^T (fp32, tiled), scatter to enqueued columns -----
__global__ __launch_bounds__(256) void fixup_gemm_kernel(const float* __restrict__ F,
                                                         const int* __restrict__ eidx) {
    __shared__ float As[64][33];
    __shared__ float Bs[64][33];
    __shared__ int   s_col[64];
    const int bj = blockIdx.x * 64;
    const int bn = blockIdx.y * 64;
    const int tid = threadIdx.x;
    const int tx = tid & 15, ty = tid >> 4;
    if (tid < 64) s_col[tid] = eidx[bj + tid];
    float acc[4][4] = {};

    for (int k0 = 0; k0 < CH; k0 += 32) {
#pragma unroll
        for (int l = 0; l < 2; l++) {
            int idx = tid + l * 256;
            int r = idx >> 3;
            int c = (idx & 7) << 2;
            float4 v = *(const float4*)&F[(size_t)(bn + r) * CH + k0 + c];
            As[r][c] = v.x; As[r][c + 1] = v.y; As[r][c + 2] = v.z; As[r][c + 3] = v.w;
            float4 w = *(const float4*)&F[(size_t)(bj + r) * CH + k0 + c];
            Bs[r][c] = w.x; Bs[r][c + 1] = w.y; Bs[r][c + 2] = w.z; Bs[r][c + 3] = w.w;
        }
        __syncthreads();
#pragma unroll
        for (int kk = 0; kk < 32; kk++) {
            float a[4], b[4];
#pragma unroll
            for (int i = 0; i < 4; i++) a[i] = As[ty * 4 + i][kk];
#pragma unroll
            for (int j = 0; j < 4; j++) b[j] = Bs[tx * 4 + j][kk];
#pragma unroll
            for (int i = 0; i < 4; i++)
#pragma unroll
                for (int j = 0; j < 4; j++) acc[i][j] += a[i] * b[j];
        }
        __syncthreads();
    }
#pragma unroll
    for (int i = 0; i < 4; i++) {
        int nrow = bn + ty * 4 + i;
#pragma unroll
        for (int j = 0; j < 4; j++)
            g_pairs[(size_t)nrow * BR + s_col[tx * 4 + j]] = acc[i][j];
    }
}

// ------------------------- helpers ------------------------------------------
__device__ __forceinline__ uint32_t fkey(float v) {
    uint32_t u = __float_as_uint(v);
    return (u & 0x80000000u) ? ~u : (u | 0x80000000u);
}
__device__ __forceinline__ float unfkey(uint32_t u) {
    uint32_t b = (u & 0x80000000u) ? (u & 0x7FFFFFFFu) : ~u;
    return __uint_as_float(b);
}

__device__ __forceinline__ int warpRedInt(int c) {
    return __reduce_add_sync(0xffffffffu, c);     // single REDUX vs 5-shfl chain
}
__device__ __forceinline__ float warpRedF(float v) {
#pragma unroll
    for (int o = 16; o > 0; o >>= 1) v += __shfl_xor_sync(0xffffffffu, v, o);
    return v;
}

// warp-private rank selection (REDUX-based, no block syncs)
__device__ uint32_t warp_sel_largest_u32(const uint32_t* a, int len, int need) {
    int lane = threadIdx.x & 31;
    uint32_t lo = 0, hi = 0xFFFFFFFFu;
    while (lo < hi) {
        uint32_t d = hi - lo;
        uint32_t mid = lo + (d >> 1) + (d & 1);
        int c = 0;
        for (int i = lane; i < len; i += 32) c += (a[i] >= mid);
        c = warpRedInt(c);
        if (c >= need) lo = mid; else hi = mid - 1;
    }
    return lo;
}
__device__ uint32_t warp_sel_smallest_u32(const uint32_t* a, int len, int need) {
    int lane = threadIdx.x & 31;
    uint32_t lo = 0, hi = 0xFFFFFFFFu;
    while (lo < hi) {
        uint32_t mid = lo + ((hi - lo) >> 1);
        int c = 0;
        for (int i = lane; i < len; i += 32) c += (a[i] <= mid);
        c = warpRedInt(c);
        if (c >= need) hi = mid; else lo = mid + 1;
    }
    return lo;
}
__device__ uint32_t warp_sel_smallest_fkey(const float* a, int len, int need) {
    int lane = threadIdx.x & 31;
    uint32_t lo = 0, hi = 0xFFFFFFFFu;
    while (lo < hi) {
        uint32_t mid = lo + ((hi - lo) >> 1);
        int c = 0;
        for (int i = lane; i < len; i += 32) c += (fkey(a[i]) <= mid);
        c = warpRedInt(c);
        if (c >= need) hi = mid; else lo = mid + 1;
    }
    return lo;
}

__device__ __forceinline__ int blockReduceInt(int c, int* s_red) {
    __syncthreads();
    if (threadIdx.x == 0) *s_red = 0;
    __syncthreads();
    c = warpRedInt(c);
    if ((threadIdx.x & 31) == 0) atomicAdd(s_red, c);
    __syncthreads();
    return *s_red;
}
__device__ __forceinline__ float blockReduceFloat(float v, float* warpBuf) {
    v = warpRedF(v);
    int lane = threadIdx.x & 31, w = threadIdx.x >> 5;
    if (lane == 0) warpBuf[w] = v;
    __syncthreads();
    float s = 0.f;
    if (threadIdx.x == 0)
        for (int i = 0; i < (int)(blockDim.x >> 5); i++) s += warpBuf[i];
    __syncthreads();
    return s;   // thread 0 only
}
__device__ __forceinline__ double blockReduceDouble(double v, double* warpBuf) {
#pragma unroll
    for (int o = 16; o > 0; o >>= 1) v += __shfl_xor_sync(0xffffffffu, v, o);
    int lane = threadIdx.x & 31, w = threadIdx.x >> 5;
    if (lane == 0) warpBuf[w] = v;
    __syncthreads();
    double s = 0.0;
    if (threadIdx.x == 0)
        for (int i = 0; i < (int)(blockDim.x >> 5); i++) s += warpBuf[i];
    __syncthreads();
    return s;   // thread 0 only
}

__device__ __forceinline__ double lterm(float pv, float Eh, float Er) {
    float e = expf(pv);
    return (double)(logf(e + Eh) - pv) + (double)(logf(e + Er) - pv);
}

// ------- fused: hard top-512 + rand 512 + pos-128 + per-row loss ------------
__global__ __launch_bounds__(512) void negsel_kernel(const int* __restrict__ label,
                                                     const float* __restrict__ rnd,
                                                     const int* __restrict__ eidx) {
    __shared__ uint32_t s_negmask[NWORDS];
    __shared__ uint32_t s_posmask[NWORDS];
    __shared__ uint32_t s_listH[CAPN];
    __shared__ u64      s_listR[CAPN];
    __shared__ uint32_t s_sampH[1024];
    __shared__ uint32_t s_sampR[1024];
    __shared__ float    s_pos[MEMSZ];
    __shared__ int      s_cntH, s_cntR, s_red;
    __shared__ float    s_warp[16];
    __shared__ double   s_warpd[16];
    __shared__ uint32_t s_thrH, s_thrP, s_thrRs;
    __shared__ u64      s_thrR;
    __shared__ float    s_Eh, s_Er;

    const int n = blockIdx.x;
    const int lbl = label[n];
    const float* row  = g_pairs + (size_t)n * BR;
    const float* rrow = rnd + (size_t)n * BR;
    const int tid = threadIdx.x, wid = tid >> 5, lane = tid & 31;

    for (int w = tid; w < NWORDS; w += 512) {
        uint32_t v = g_validbits[w], e = g_eqtab[lbl * 15 + (w % 15)];
        s_negmask[w] = v & ~e;
        s_posmask[w] = v & e;
    }
    for (int i = tid; i < MEMSZ; i += 512) s_pos[i] = INFINITY;
    if (tid == 0) { s_cntH = 0; s_cntR = 0; }
    __syncthreads();
    {   // fold enqueue scatter: those columns become valid
        int j = eidx[tid];
        uint32_t bit = 1u << (j & 31);
        if (j % CLS == lbl) atomicOr(&s_posmask[j >> 5], bit);
        else                atomicOr(&s_negmask[j >> 5], bit);
    }
    __syncthreads();

    // ---- 1024 deterministic samples each for hard & rand -------------------
    for (int s = tid; s < 1024; s += 512) {
        int j = 37 * s + 11;
        bool ok = (s_negmask[j >> 5] >> (j & 31)) & 1;
        s_sampH[s] = ok ? fkey(row[j]) : 0u;                      // -inf key
        s_sampR[s] = ok ? __float_as_uint(rrow[j]) : 0xFFFFFFFFu; // huge key
    }
    __syncthreads();
    if (wid == 0) { uint32_t t = warp_sel_largest_u32(s_sampH, 1024, 32);
                    if (lane == 0) s_thrH = t; }
    if (wid == 1) { uint32_t t = warp_sel_smallest_u32(s_sampR, 1024, 32);
                    if (lane == 0) s_thrRs = t; }
    __syncthreads();
    const float thrHs = unfkey(s_thrH);
    const float thrRs = __uint_as_float(s_thrRs);

    // ---- single fused scan --------------------------------------------------
    for (int q = tid; q < NQ; q += 512) {
        uint32_t nm = (s_negmask[q >> 3] >> ((q & 7) << 2)) & 0xF;
        uint32_t pm = (s_posmask[q >> 3] >> ((q & 7) << 2)) & 0xF;
        if (!(nm | pm)) continue;
        float4 v = ((const float4*)row)[q];
        float vv[4] = {v.x, v.y, v.z, v.w};
        int j0 = q << 2;
        if (pm) {
#pragma unroll
            for (int e = 0; e < 4; e++)
                if ((pm >> e) & 1)
                    s_pos[(unsigned)(j0 + e - lbl) / 60u] = vv[e];
        }
        if (nm) {
            float4 r = ((const float4*)rrow)[q];
            float rr[4] = {r.x, r.y, r.z, r.w};
#pragma unroll
            for (int e = 0; e < 4; e++) {
                if ((nm >> e) & 1) {
                    if (vv[e] >= thrHs) {
                        int p = atomicAdd(&s_cntH, 1);
                        if (p < CAPN) s_listH[p] = fkey(vv[e]);
                    }
                    if (rr[e] <= thrRs) {
                        int p = atomicAdd(&s_cntR, 1);
                        if (p < CAPN)
                            s_listR[p] = ((u64)__float_as_uint(rr[e]) << 32) |
                                         (unsigned)(j0 + e);
                    }
                }
            }
        }
    }
    __syncthreads();
    const int cntH = s_cntH, cntR = s_cntR;
    const bool okH = (cntH >= NEGN && cntH <= CAPN);
    const bool okR = (cntR >= NEGN && cntR <= CAPN);

    // ---- warp0: hard thr + Eh; warp1: rand 2-stage + Er; warp2: pos ---------
    if (okH && wid == 0) {
        uint32_t t = warp_sel_largest_u32(s_listH, cntH, NEGN);
        int cg = 0; float se = 0.f;
        for (int i = lane; i < cntH; i += 32) {
            uint32_t u = s_listH[i];
            if (u > t) { cg++; se += expf(unfkey(u)); }
        }
        cg = warpRedInt(cg); se = warpRedF(se);
        if (lane == 0) s_Eh = se + (float)(NEGN - cg) * expf(unfkey(t));
    }
    if (okR && wid == 1) {
        // stage 1: bisect the 32-bit rand key (32 iters, not 64)
        uint32_t lo = 0, hi = 0xFFFFFFFFu;
        while (lo < hi) {
            uint32_t mid = lo + ((hi - lo) >> 1);
            int c = 0;
            for (int i = lane; i < cntR; i += 32)
                c += ((uint32_t)(s_listR[i] >> 32) <= mid);
            c = warpRedInt(c);
            if (c >= NEGN) hi = mid; else lo = mid + 1;
        }
        const uint32_t kv = lo;
        int cl = 0, ce = 0;
        for (int i = lane; i < cntR; i += 32) {
            uint32_t k = (uint32_t)(s_listR[i] >> 32);
            cl += (k < kv); ce += (k == kv);
        }
        cl = warpRedInt(cl); ce = warpRedInt(ce);
        const int need2 = NEGN - cl;
        uint32_t ti = 0xFFFFFFFFu;
        if (ce != need2) {           // rare key-tie: bisect index among equals
            uint32_t l2 = 0, h2 = 0xFFFFFFFFu;
            while (l2 < h2) {
                uint32_t mid = l2 + ((h2 - l2) >> 1);
                int c = 0;
                for (int i = lane; i < cntR; i += 32) {
                    u64 w = s_listR[i];
                    c += (((uint32_t)(w >> 32) == kv) && ((uint32_t)w <= mid));
                }
                c = warpRedInt(c);
                if (c >= need2) h2 = mid; else l2 = mid + 1;
            }
            ti = l2;
        }
        float se = 0.f;
        for (int i = lane; i < cntR; i += 32) {
            u64 w = s_listR[i];
            uint32_t k = (uint32_t)(w >> 32);
            if (k < kv || (k == kv && (uint32_t)w <= ti))
                se += expf(row[(uint32_t)w]);
        }
        se = warpRedF(se);
        if (lane == 0) s_Er = se;
    }
    if (wid == 2) {
        uint32_t t = warp_sel_smallest_fkey(s_pos, MEMSZ, POSN);
        if (lane == 0) s_thrP = t;
    }
    __syncthreads();

    // ---- rare fallbacks: block-wide bisect over gmem ------------------------
    if (!okH) {
        uint32_t lo = 0, hi = 0xFFFFFFFFu;
        while (lo < hi) {
            uint32_t d = hi - lo;
            uint32_t mid = lo + (d >> 1) + (d & 1);
            int c = 0;
            for (int j = tid; j < BR; j += 512)
                if ((s_negmask[j >> 5] >> (j & 31)) & 1) c += (fkey(row[j]) >= mid);
            c = blockReduceInt(c, &s_red);
            if (c >= NEGN) lo = mid; else hi = mid - 1;
        }
        uint32_t t = lo;
        int cg = 0; float se = 0.f;
        for (int j = tid; j < BR; j += 512)
            if ((s_negmask[j >> 5] >> (j & 31)) & 1) {
                float x = row[j];
                if (fkey(x) > t) { cg++; se += expf(x); }
            }
        cg = blockReduceInt(cg, &s_red);
        float tot = blockReduceFloat(se, s_warp);
        if (tid == 0) s_Eh = tot + (float)(NEGN - cg) * expf(unfkey(t));
        __syncthreads();
    }
    if (!okR) {
        u64 lo = 0ull, hi = 0xFFFFFFFFFFFFFFFFull;
        while (lo < hi) {
            u64 mid = lo + ((hi - lo) >> 1);
            int c = 0;
            for (int j = tid; j < BR; j += 512)
                if ((s_negmask[j >> 5] >> (j & 31)) & 1) {
                    u64 w = ((u64)__float_as_uint(rrow[j]) << 32) | (unsigned)j;
                    c += (w <= mid);
                }
            c = blockReduceInt(c, &s_red);
            if (c >= NEGN) hi = mid; else lo = mid + 1;
        }
        const u64 t = lo;
        float se = 0.f;
        for (int j = tid; j < BR; j += 512)
            if ((s_negmask[j >> 5] >> (j & 31)) & 1) {
                u64 w = ((u64)__float_as_uint(rrow[j]) << 32) | (unsigned)j;
                if (w <= t) se += expf(row[j]);
            }
        float tot = blockReduceFloat(se, s_warp);
        if (tid == 0) s_Er = tot;
        __syncthreads();
    }

    // ---- per-row loss: 128 smallest pos values (with ties) ------------------
    const float Eh = s_Eh, Er = s_Er;
    const uint32_t tP = s_thrP;
    int c = 0; double ts = 0.0;
    for (int i = tid; i < MEMSZ; i += 512) {
        float pv = s_pos[i];
        if (fkey(pv) < tP) { c++; ts += lterm(pv, Eh, Er); }
    }
    c = blockReduceInt(c, &s_red);
    double tsum = blockReduceDouble(ts, s_warpd);
    if (tid == 0) {
        tsum += (double)(POSN - c) * lterm(unfkey(tP), Eh, Er);
        atomicAdd(&g_loss, tsum);
    }
}

__global__ void finalize_kernel(float* out) {
    out[0] = (float)(g_loss / (double)(BATCH * 2 * POSN));
}

// ------------------------- launcher -----------------------------------------
extern "C" void kernel_launch(void* const* d_in, const int* in_sizes, int n_in,
                              void* d_out, int out_size) {
    const float* f    = (const float*)d_in[0];
    const int*   lab  = (const int*)d_in[1];
    const int*   eidx = (const int*)d_in[2];
    const float* bank = (const float*)d_in[3];
    const float* flag = (const float*)d_in[4];
    const float* rnd  = (const float*)d_in[5];
    float* out = (float*)d_out;

    const int GEMM_SMEM = 2 * 2 * GBM * GPAD * 4;   // 73728 bytes
    cudaFuncSetAttribute(gemm_tf32_kernel,
                         cudaFuncAttributeMaxDynamicSharedMemorySize, GEMM_SMEM);

    prep_kernel<<<6, 256>>>(flag);
    scatter_kernel<<<2, 256>>>(eidx);
    gemm_tf32_kernel<<<dim3((BR + GBN - 1) / GBN, BATCH / GBM), 128, GEMM_SMEM>>>(f, bank);
    fixup_gemm_kernel<<<dim3(BATCH / 64, BATCH / 64), 256>>>(f, eidx);
    negsel_kernel<<<BATCH, 512>>>(lab, rnd, eidx);
    finalize_kernel<<<1, 1>>>(out);
    (void)in_sizes; (void)n_in; (void)out_size;
}

// round 14
// speedup vs baseline: 2.4759x; 1.3022x over previous
#include <cuda_runtime.h>
#include <math.h>
#include <stdint.h>

#define BATCH 512
#define CH    256
#define CLS   60
#define MEMSZ 684
#define BR    41040
#define POSN  128
#define NEGN  512
#define NWORDS 1283          // ceil(BR/32)
#define CAPN  2048
#define NQ    (BR/4)         // 10260 float4 per row

// Fixed selection thresholds (statistical prefilter only; exact fallback
// guarantees correctness regardless). Dots ~ N(0, 1/16): P(v>=0.12)*40356
// ~= 1110 candidates. Rand ~ U[0,1): P(r<=0.0155)*40356 ~= 628.
#define THR_HARD 0.12f
#define THR_RAND 0.0155f

typedef unsigned long long u64;

// ------------------------- device scratch -----------------------------------
__device__ float    g_pairs[(size_t)BATCH * BR];   // 84 MB
__device__ uint32_t g_validbits[NWORDS];
__device__ uint32_t g_eqtab[CLS * 15];
__device__ double   g_loss;

// ------------------------- prep ---------------------------------------------
__global__ void prep_kernel(const float* __restrict__ flag) {
    int i = blockIdx.x * blockDim.x + threadIdx.x;
    if (i == 0) g_loss = 0.0;
    if (i < CLS * 15) {
        int lbl = i / 15, p = i % 15;
        int off = (32 * p) % 60;
        uint32_t m = 0;
        for (int b = 0; b < 32; b++) if ((off + b) % 60 == lbl) m |= 1u << b;
        g_eqtab[i] = m;
    }
    if (i < NWORDS) {
        uint32_t m = 0; int base = i * 32;
        for (int b = 0; b < 32; b++) {
            int j = base + b;
            if (j < BR && flag[j] > 0.f) m |= 1u << b;
        }
        g_validbits[i] = m;
    }
}

__global__ void scatter_kernel(const int* __restrict__ eidx) {
    int m = blockIdx.x * blockDim.x + threadIdx.x;
    if (m < BATCH) { int j = eidx[m]; atomicOr(&g_validbits[j >> 5], 1u << (j & 31)); }
}

// ------------------------- tf32 tensor-core GEMM (proven 128x128) -----------
#define GBM 128
#define GBN 128
#define GBK 32
#define GPAD 36
#define GKITERS 8

__device__ __forceinline__ void mma_tf32(float* c, const uint32_t* a, const uint32_t* b) {
    asm volatile(
        "mma.sync.aligned.m16n8k8.row.col.f32.tf32.tf32.f32 "
        "{%0,%1,%2,%3},{%4,%5,%6,%7},{%8,%9},{%0,%1,%2,%3};"
        : "+f"(c[0]), "+f"(c[1]), "+f"(c[2]), "+f"(c[3])
        : "r"(a[0]), "r"(a[1]), "r"(a[2]), "r"(a[3]), "r"(b[0]), "r"(b[1]));
}

__global__ __launch_bounds__(128) void gemm_tf32_kernel(const float* __restrict__ F,
                                                        const float* __restrict__ BK_) {
    extern __shared__ float sm[];
    float* As = sm;
    float* Bs = sm + 2 * GBM * GPAD;
#define ASM(bf, r, c) As[(bf) * GBM * GPAD + (r) * GPAD + (c)]
#define BSM(bf, r, c) Bs[(bf) * GBM * GPAD + (r) * GPAD + (c)]

    const int bj = blockIdx.x * GBN;
    const int bn = blockIdx.y * GBM;
    const int tid = threadIdx.x;
    const int wid = tid >> 5, lane = tid & 31;
    const int wm = (wid >> 1) * 64, wn = (wid & 1) * 64;
    const int tr = lane >> 2, tc = lane & 3;

    float acc[4][8][4];
#pragma unroll
    for (int i = 0; i < 4; i++)
#pragma unroll
        for (int j = 0; j < 8; j++)
#pragma unroll
            for (int k = 0; k < 4; k++) acc[i][j][k] = 0.f;

    auto load_stage = [&](int buf, int kt) {
        int k0 = kt * GBK;
#pragma unroll
        for (int i = 0; i < 8; i++) {
            int slot = tid + i * 128;
            int r = slot >> 3;
            int kq = (slot & 7) * 4;
            uint32_t da = (uint32_t)__cvta_generic_to_shared(&ASM(buf, r, kq));
            const float* ga = F + (size_t)(bn + r) * CH + k0 + kq;
            asm volatile("cp.async.cg.shared.global [%0], [%1], 16;" :: "r"(da), "l"(ga));
            int j = bj + r;
            int ok = (j < BR) ? 16 : 0;
            const float* gb = BK_ + (size_t)(j < BR ? j : 0) * CH + k0 + kq;
            uint32_t db = (uint32_t)__cvta_generic_to_shared(&BSM(buf, r, kq));
            asm volatile("cp.async.cg.shared.global [%0], [%1], 16, %2;" :: "r"(db), "l"(gb), "r"(ok));
        }
    };

    load_stage(0, 0);
    asm volatile("cp.async.commit_group;");

    for (int kt = 0; kt < GKITERS; kt++) {
        asm volatile("cp.async.wait_group 0;");
        __syncthreads();
        if (kt + 1 < GKITERS) {
            load_stage((kt + 1) & 1, kt + 1);
            asm volatile("cp.async.commit_group;");
        }
        int b = kt & 1;
#pragma unroll
        for (int ks = 0; ks < 4; ks++) {
            int kk = ks * 8;
            uint32_t af[4][4], bf[8][2];
#pragma unroll
            for (int mi = 0; mi < 4; mi++) {
                int r0 = wm + mi * 16 + tr;
                af[mi][0] = __float_as_uint(ASM(b, r0,     kk + tc));
                af[mi][1] = __float_as_uint(ASM(b, r0 + 8, kk + tc));
                af[mi][2] = __float_as_uint(ASM(b, r0,     kk + tc + 4));
                af[mi][3] = __float_as_uint(ASM(b, r0 + 8, kk + tc + 4));
            }
#pragma unroll
            for (int ni = 0; ni < 8; ni++) {
                int r0 = wn + ni * 8 + tr;
                bf[ni][0] = __float_as_uint(BSM(b, r0, kk + tc));
                bf[ni][1] = __float_as_uint(BSM(b, r0, kk + tc + 4));
            }
#pragma unroll
            for (int mi = 0; mi < 4; mi++)
#pragma unroll
                for (int ni = 0; ni < 8; ni++) mma_tf32(acc[mi][ni], af[mi], bf[ni]);
        }
    }

#pragma unroll
    for (int mi = 0; mi < 4; mi++) {
        int m = bn + wm + mi * 16 + tr;
        float* p0 = &g_pairs[(size_t)m * BR];
        float* p1 = &g_pairs[(size_t)(m + 8) * BR];
#pragma unroll
        for (int ni = 0; ni < 8; ni++) {
            int col = bj + wn + ni * 8 + tc * 2;
            if (col < BR) {
                *(float2*)(p0 + col) = make_float2(acc[mi][ni][0], acc[mi][ni][1]);
                *(float2*)(p1 + col) = make_float2(acc[mi][ni][2], acc[mi][ni][3]);
            }
        }
    }
#undef ASM
#undef BSM
}

// -------- fixup: S = F @ F^T (fp32), 64col x 32row tiles (128 blocks) -------
__global__ __launch_bounds__(256) void fixup_gemm_kernel(const float* __restrict__ F,
                                                         const int* __restrict__ eidx) {
    __shared__ float As[32][33];     // batch rows
    __shared__ float Bs[64][33];     // enqueue-slot rows
    __shared__ int   s_col[64];
    const int bj = blockIdx.x * 64;  // enqueue slot base
    const int bn = blockIdx.y * 32;  // batch row base
    const int tid = threadIdx.x;
    const int tx = tid & 15, ty = tid >> 4;
    if (tid < 64) s_col[tid] = eidx[bj + tid];
    float acc[2][4] = {};

    for (int k0 = 0; k0 < CH; k0 += 32) {
        {   // A: 32 rows x 8 float4 = 256 slots, 1 per thread
            int r = tid >> 3;
            int c = (tid & 7) << 2;
            float4 v = *(const float4*)&F[(size_t)(bn + r) * CH + k0 + c];
            As[r][c] = v.x; As[r][c + 1] = v.y; As[r][c + 2] = v.z; As[r][c + 3] = v.w;
        }
#pragma unroll
        for (int l = 0; l < 2; l++) {   // B: 64 rows x 8 float4 = 512 slots
            int idx = tid + l * 256;
            int r = idx >> 3;
            int c = (idx & 7) << 2;
            float4 w = *(const float4*)&F[(size_t)(bj + r) * CH + k0 + c];
            Bs[r][c] = w.x; Bs[r][c + 1] = w.y; Bs[r][c + 2] = w.z; Bs[r][c + 3] = w.w;
        }
        __syncthreads();
#pragma unroll
        for (int kk = 0; kk < 32; kk++) {
            float a[2], b[4];
#pragma unroll
            for (int i = 0; i < 2; i++) a[i] = As[ty * 2 + i][kk];
#pragma unroll
            for (int j = 0; j < 4; j++) b[j] = Bs[tx * 4 + j][kk];
#pragma unroll
            for (int i = 0; i < 2; i++)
#pragma unroll
                for (int j = 0; j < 4; j++) acc[i][j] += a[i] * b[j];
        }
        __syncthreads();
    }
#pragma unroll
    for (int i = 0; i < 2; i++) {
        int nrow = bn + ty * 2 + i;
#pragma unroll
        for (int j = 0; j < 4; j++)
            g_pairs[(size_t)nrow * BR + s_col[tx * 4 + j]] = acc[i][j];
    }
}

// ------------------------- helpers ------------------------------------------
__device__ __forceinline__ uint32_t fkey(float v) {
    uint32_t u = __float_as_uint(v);
    return (u & 0x80000000u) ? ~u : (u | 0x80000000u);
}
__device__ __forceinline__ float unfkey(uint32_t u) {
    uint32_t b = (u & 0x80000000u) ? (u & 0x7FFFFFFFu) : ~u;
    return __uint_as_float(b);
}

__device__ __forceinline__ int warpRedInt(int c) {
    return __reduce_add_sync(0xffffffffu, c);
}
__device__ __forceinline__ float warpRedF(float v) {
#pragma unroll
    for (int o = 16; o > 0; o >>= 1) v += __shfl_xor_sync(0xffffffffu, v, o);
    return v;
}

__device__ uint32_t warp_sel_largest_u32(const uint32_t* a, int len, int need) {
    int lane = threadIdx.x & 31;
    uint32_t lo = 0, hi = 0xFFFFFFFFu;
    while (lo < hi) {
        uint32_t d = hi - lo;
        uint32_t mid = lo + (d >> 1) + (d & 1);
        int c = 0;
        for (int i = lane; i < len; i += 32) c += (a[i] >= mid);
        c = warpRedInt(c);
        if (c >= need) lo = mid; else hi = mid - 1;
    }
    return lo;
}
__device__ uint32_t warp_sel_smallest_fkey(const float* a, int len, int need) {
    int lane = threadIdx.x & 31;
    uint32_t lo = 0, hi = 0xFFFFFFFFu;
    while (lo < hi) {
        uint32_t mid = lo + ((hi - lo) >> 1);
        int c = 0;
        for (int i = lane; i < len; i += 32) c += (fkey(a[i]) <= mid);
        c = warpRedInt(c);
        if (c >= need) hi = mid; else lo = mid + 1;
    }
    return lo;
}

__device__ __forceinline__ int blockReduceInt(int c, int* s_red) {
    __syncthreads();
    if (threadIdx.x == 0) *s_red = 0;
    __syncthreads();
    c = warpRedInt(c);
    if ((threadIdx.x & 31) == 0) atomicAdd(s_red, c);
    __syncthreads();
    return *s_red;
}
__device__ __forceinline__ float blockReduceFloat(float v, float* warpBuf) {
    v = warpRedF(v);
    int lane = threadIdx.x & 31, w = threadIdx.x >> 5;
    if (lane == 0) warpBuf[w] = v;
    __syncthreads();
    float s = 0.f;
    if (threadIdx.x == 0)
        for (int i = 0; i < (int)(blockDim.x >> 5); i++) s += warpBuf[i];
    __syncthreads();
    return s;   // thread 0 only
}
__device__ __forceinline__ double blockReduceDouble(double v, double* warpBuf) {
#pragma unroll
    for (int o = 16; o > 0; o >>= 1) v += __shfl_xor_sync(0xffffffffu, v, o);
    int lane = threadIdx.x & 31, w = threadIdx.x >> 5;
    if (lane == 0) warpBuf[w] = v;
    __syncthreads();
    double s = 0.0;
    if (threadIdx.x == 0)
        for (int i = 0; i < (int)(blockDim.x >> 5); i++) s += warpBuf[i];
    __syncthreads();
    return s;   // thread 0 only
}

__device__ __forceinline__ double lterm(float pv, float Eh, float Er) {
    float e = expf(pv);
    return (double)(logf(e + Eh) - pv) + (double)(logf(e + Er) - pv);
}

// ------- fused: hard top-512 + rand 512 + pos-128 + per-row loss ------------
__global__ __launch_bounds__(512) void negsel_kernel(const int* __restrict__ label,
                                                     const float* __restrict__ rnd,
                                                     const int* __restrict__ eidx) {
    __shared__ uint32_t s_negmask[NWORDS];
    __shared__ uint32_t s_posmask[NWORDS];
    __shared__ uint32_t s_listH[CAPN];
    __shared__ u64      s_listR[CAPN];
    __shared__ float    s_pos[MEMSZ];
    __shared__ int      s_cntH, s_cntR, s_red;
    __shared__ float    s_warp[16];
    __shared__ double   s_warpd[16];
    __shared__ uint32_t s_thrH, s_thrP;
    __shared__ u64      s_thrR;
    __shared__ float    s_Eh, s_Er;

    const int n = blockIdx.x;
    const int lbl = label[n];
    const float* row  = g_pairs + (size_t)n * BR;
    const float* rrow = rnd + (size_t)n * BR;
    const int tid = threadIdx.x, wid = tid >> 5, lane = tid & 31;

    for (int w = tid; w < NWORDS; w += 512) {
        uint32_t v = g_validbits[w], e = g_eqtab[lbl * 15 + (w % 15)];
        s_negmask[w] = v & ~e;
        s_posmask[w] = v & e;
    }
    for (int i = tid; i < MEMSZ; i += 512) s_pos[i] = INFINITY;
    if (tid == 0) { s_cntH = 0; s_cntR = 0; }
    __syncthreads();
    {   // fold enqueue scatter (redundant with scatter_kernel; harmless)
        int j = eidx[tid];
        uint32_t bit = 1u << (j & 31);
        if (j % CLS == lbl) atomicOr(&s_posmask[j >> 5], bit);
        else                atomicOr(&s_negmask[j >> 5], bit);
    }
    __syncthreads();

    // ---- fixed prefilter thresholds (exactness via fallback) ----------------
    const float thrHs = THR_HARD;
    const float thrRs = THR_RAND;

    // ---- single fused scan --------------------------------------------------
    for (int q = tid; q < NQ; q += 512) {
        uint32_t nm = (s_negmask[q >> 3] >> ((q & 7) << 2)) & 0xF;
        uint32_t pm = (s_posmask[q >> 3] >> ((q & 7) << 2)) & 0xF;
        if (!(nm | pm)) continue;
        float4 v = ((const float4*)row)[q];
        float vv[4] = {v.x, v.y, v.z, v.w};
        int j0 = q << 2;
        if (pm) {
#pragma unroll
            for (int e = 0; e < 4; e++)
                if ((pm >> e) & 1)
                    s_pos[(unsigned)(j0 + e - lbl) / 60u] = vv[e];
        }
        if (nm) {
            float4 r = ((const float4*)rrow)[q];
            float rr[4] = {r.x, r.y, r.z, r.w};
#pragma unroll
            for (int e = 0; e < 4; e++) {
                if ((nm >> e) & 1) {
                    if (vv[e] >= thrHs) {
                        int p = atomicAdd(&s_cntH, 1);
                        if (p < CAPN) s_listH[p] = fkey(vv[e]);
                    }
                    if (rr[e] <= thrRs) {
                        int p = atomicAdd(&s_cntR, 1);
                        if (p < CAPN)
                            s_listR[p] = ((u64)__float_as_uint(rr[e]) << 32) |
                                         (unsigned)(j0 + e);
                    }
                }
            }
        }
    }
    __syncthreads();
    const int cntH = s_cntH, cntR = s_cntR;
    const bool okH = (cntH >= NEGN && cntH <= CAPN);
    const bool okR = (cntR >= NEGN && cntR <= CAPN);

    // ---- warp0: hard thr + Eh; warp1: rand 2-stage + Er; warp2: pos ---------
    if (okH && wid == 0) {
        uint32_t t = warp_sel_largest_u32(s_listH, cntH, NEGN);
        int cg = 0; float se = 0.f;
        for (int i = lane; i < cntH; i += 32) {
            uint32_t u = s_listH[i];
            if (u > t) { cg++; se += expf(unfkey(u)); }
        }
        cg = warpRedInt(cg); se = warpRedF(se);
        if (lane == 0) s_Eh = se + (float)(NEGN - cg) * expf(unfkey(t));
    }
    if (okR && wid == 1) {
        // stage 1: bisect the 32-bit rand key
        uint32_t lo = 0, hi = 0xFFFFFFFFu;
        while (lo < hi) {
            uint32_t mid = lo + ((hi - lo) >> 1);
            int c = 0;
            for (int i = lane; i < cntR; i += 32)
                c += ((uint32_t)(s_listR[i] >> 32) <= mid);
            c = warpRedInt(c);
            if (c >= NEGN) hi = mid; else lo = mid + 1;
        }
        const uint32_t kv = lo;
        int cl = 0, ce = 0;
        for (int i = lane; i < cntR; i += 32) {
            uint32_t k = (uint32_t)(s_listR[i] >> 32);
            cl += (k < kv); ce += (k == kv);
        }
        cl = warpRedInt(cl); ce = warpRedInt(ce);
        const int need2 = NEGN - cl;
        uint32_t ti = 0xFFFFFFFFu;
        if (ce != need2) {           // rare key-tie: bisect index among equals
            uint32_t l2 = 0, h2 = 0xFFFFFFFFu;
            while (l2 < h2) {
                uint32_t mid = l2 + ((h2 - l2) >> 1);
                int c = 0;
                for (int i = lane; i < cntR; i += 32) {
                    u64 w = s_listR[i];
                    c += (((uint32_t)(w >> 32) == kv) && ((uint32_t)w <= mid));
                }
                c = warpRedInt(c);
                if (c >= need2) h2 = mid; else l2 = mid + 1;
            }
            ti = l2;
        }
        float se = 0.f;
        for (int i = lane; i < cntR; i += 32) {
            u64 w = s_listR[i];
            uint32_t k = (uint32_t)(w >> 32);
            if (k < kv || (k == kv && (uint32_t)w <= ti))
                se += expf(row[(uint32_t)w]);
        }
        se = warpRedF(se);
        if (lane == 0) s_Er = se;
    }
    if (wid == 2) {
        uint32_t t = warp_sel_smallest_fkey(s_pos, MEMSZ, POSN);
        if (lane == 0) s_thrP = t;
    }
    __syncthreads();

    // ---- rare fallbacks: block-wide bisect over gmem (exactness net) --------
    if (!okH) {
        uint32_t lo = 0, hi = 0xFFFFFFFFu;
        while (lo < hi) {
            uint32_t d = hi - lo;
            uint32_t mid = lo + (d >> 1) + (d & 1);
            int c = 0;
            for (int j = tid; j < BR; j += 512)
                if ((s_negmask[j >> 5] >> (j & 31)) & 1) c += (fkey(row[j]) >= mid);
            c = blockReduceInt(c, &s_red);
            if (c >= NEGN) lo = mid; else hi = mid - 1;
        }
        uint32_t t = lo;
        int cg = 0; float se = 0.f;
        for (int j = tid; j < BR; j += 512)
            if ((s_negmask[j >> 5] >> (j & 31)) & 1) {
                float x = row[j];
                if (fkey(x) > t) { cg++; se += expf(x); }
            }
        cg = blockReduceInt(cg, &s_red);
        float tot = blockReduceFloat(se, s_warp);
        if (tid == 0) s_Eh = tot + (float)(NEGN - cg) * expf(unfkey(t));
        __syncthreads();
    }
    if (!okR) {
        u64 lo = 0ull, hi = 0xFFFFFFFFFFFFFFFFull;
        while (lo < hi) {
            u64 mid = lo + ((hi - lo) >> 1);
            int c = 0;
            for (int j = tid; j < BR; j += 512)
                if ((s_negmask[j >> 5] >> (j & 31)) & 1) {
                    u64 w = ((u64)__float_as_uint(rrow[j]) << 32) | (unsigned)j;
                    c += (w <= mid);
                }
            c = blockReduceInt(c, &s_red);
            if (c >= NEGN) hi = mid; else lo = mid + 1;
        }
        const u64 t = lo;
        float se = 0.f;
        for (int j = tid; j < BR; j += 512)
            if ((s_negmask[j >> 5] >> (j & 31)) & 1) {
                u64 w = ((u64)__float_as_uint(rrow[j]) << 32) | (unsigned)j;
                if (w <= t) se += expf(row[j]);
            }
        float tot = blockReduceFloat(se, s_warp);
        if (tid == 0) s_Er = tot;
        __syncthreads();
    }

    // ---- per-row loss: 128 smallest pos values (with ties) ------------------
    const float Eh = s_Eh, Er = s_Er;
    const uint32_t tP = s_thrP;
    int c = 0; double ts = 0.0;
    for (int i = tid; i < MEMSZ; i += 512) {
        float pv = s_pos[i];
        if (fkey(pv) < tP) { c++; ts += lterm(pv, Eh, Er); }
    }
    c = blockReduceInt(c, &s_red);
    double tsum = blockReduceDouble(ts, s_warpd);
    if (tid == 0) {
        tsum += (double)(POSN - c) * lterm(unfkey(tP), Eh, Er);
        atomicAdd(&g_loss, tsum);
    }
}

__global__ void finalize_kernel(float* out) {
    out[0] = (float)(g_loss / (double)(BATCH * 2 * POSN));
}

// ------------------------- launcher -----------------------------------------
extern "C" void kernel_launch(void* const* d_in, const int* in_sizes, int n_in,
                              void* d_out, int out_size) {
    const float* f    = (const float*)d_in[0];
    const int*   lab  = (const int*)d_in[1];
    const int*   eidx = (const int*)d_in[2];
    const float* bank = (const float*)d_in[3];
    const float* flag = (const float*)d_in[4];
    const float* rnd  = (const float*)d_in[5];
    float* out = (float*)d_out;

    const int GEMM_SMEM = 2 * 2 * GBM * GPAD * 4;   // 73728 bytes
    cudaFuncSetAttribute(gemm_tf32_kernel,
                         cudaFuncAttributeMaxDynamicSharedMemorySize, GEMM_SMEM);

    prep_kernel<<<6, 256>>>(flag);
    scatter_kernel<<<2, 256>>>(eidx);
    gemm_tf32_kernel<<<dim3((BR + GBN - 1) / GBN, BATCH / GBM), 128, GEMM_SMEM>>>(f, bank);
    fixup_gemm_kernel<<<dim3(BATCH / 64, BATCH / 32), 256>>>(f, eidx);
    negsel_kernel<<<BATCH, 512>>>(lab, rnd, eidx);
    finalize_kernel<<<1, 1>>>(out);
    (void)in_sizes; (void)n_in; (void)out_size;
}

// round 15
// speedup vs baseline: 2.4863x; 1.0042x over previous
#include <cuda_runtime.h>
#include <cuda_fp16.h>
#include <math.h>
#include <stdint.h>

#define BATCH 512
#define CH    256
#define CLS   60
#define MEMSZ 684
#define BR    41040
#define POSN  128
#define NEGN  512
#define NWORDS 1283          // ceil(BR/32)
#define CAPN  2048
#define NQ    (BR/4)         // 10260 4-elem groups per row

// Fixed selection thresholds (statistical prefilter; exact fallback covers
// any out-of-range count). Dots ~ N(0, 1/256): P(v>=0.12)*40356 ~= 1110.
// Rand ~ U[0,1): P(r<=0.0155)*40356 ~= 628.
#define THR_HARD 0.12f
#define THR_RAND 0.0155f

typedef unsigned long long u64;

// ------------------------- device scratch -----------------------------------
__device__ __half   g_pairs[(size_t)BATCH * BR];   // 42 MB (fp16 logits)
__device__ uint32_t g_validbits[NWORDS];
__device__ uint32_t g_eqtab[CLS * 15];
__device__ double   g_loss;

// ------------------------- prep ---------------------------------------------
__global__ void prep_kernel(const float* __restrict__ flag) {
    int i = blockIdx.x * blockDim.x + threadIdx.x;
    if (i == 0) g_loss = 0.0;
    if (i < CLS * 15) {
        int lbl = i / 15, p = i % 15;
        int off = (32 * p) % 60;
        uint32_t m = 0;
        for (int b = 0; b < 32; b++) if ((off + b) % 60 == lbl) m |= 1u << b;
        g_eqtab[i] = m;
    }
    if (i < NWORDS) {
        uint32_t m = 0; int base = i * 32;
        for (int b = 0; b < 32; b++) {
            int j = base + b;
            if (j < BR && flag[j] > 0.f) m |= 1u << b;
        }
        g_validbits[i] = m;
    }
}

__global__ void scatter_kernel(const int* __restrict__ eidx) {
    int m = blockIdx.x * blockDim.x + threadIdx.x;
    if (m < BATCH) { int j = eidx[m]; atomicOr(&g_validbits[j >> 5], 1u << (j & 31)); }
}

// ------------------------- tf32 tensor-core GEMM (fp16 output) --------------
#define GBM 128
#define GBN 128
#define GBK 32
#define GPAD 36
#define GKITERS 8

__device__ __forceinline__ void mma_tf32(float* c, const uint32_t* a, const uint32_t* b) {
    asm volatile(
        "mma.sync.aligned.m16n8k8.row.col.f32.tf32.tf32.f32 "
        "{%0,%1,%2,%3},{%4,%5,%6,%7},{%8,%9},{%0,%1,%2,%3};"
        : "+f"(c[0]), "+f"(c[1]), "+f"(c[2]), "+f"(c[3])
        : "r"(a[0]), "r"(a[1]), "r"(a[2]), "r"(a[3]), "r"(b[0]), "r"(b[1]));
}

__global__ __launch_bounds__(128) void gemm_tf32_kernel(const float* __restrict__ F,
                                                        const float* __restrict__ BK_) {
    extern __shared__ float sm[];
    float* As = sm;
    float* Bs = sm + 2 * GBM * GPAD;
#define ASM(bf, r, c) As[(bf) * GBM * GPAD + (r) * GPAD + (c)]
#define BSM(bf, r, c) Bs[(bf) * GBM * GPAD + (r) * GPAD + (c)]

    const int bj = blockIdx.x * GBN;
    const int bn = blockIdx.y * GBM;
    const int tid = threadIdx.x;
    const int wid = tid >> 5, lane = tid & 31;
    const int wm = (wid >> 1) * 64, wn = (wid & 1) * 64;
    const int tr = lane >> 2, tc = lane & 3;

    float acc[4][8][4];
#pragma unroll
    for (int i = 0; i < 4; i++)
#pragma unroll
        for (int j = 0; j < 8; j++)
#pragma unroll
            for (int k = 0; k < 4; k++) acc[i][j][k] = 0.f;

    auto load_stage = [&](int buf, int kt) {
        int k0 = kt * GBK;
#pragma unroll
        for (int i = 0; i < 8; i++) {
            int slot = tid + i * 128;
            int r = slot >> 3;
            int kq = (slot & 7) * 4;
            uint32_t da = (uint32_t)__cvta_generic_to_shared(&ASM(buf, r, kq));
            const float* ga = F + (size_t)(bn + r) * CH + k0 + kq;
            asm volatile("cp.async.cg.shared.global [%0], [%1], 16;" :: "r"(da), "l"(ga));
            int j = bj + r;
            int ok = (j < BR) ? 16 : 0;
            const float* gb = BK_ + (size_t)(j < BR ? j : 0) * CH + k0 + kq;
            uint32_t db = (uint32_t)__cvta_generic_to_shared(&BSM(buf, r, kq));
            asm volatile("cp.async.cg.shared.global [%0], [%1], 16, %2;" :: "r"(db), "l"(gb), "r"(ok));
        }
    };

    load_stage(0, 0);
    asm volatile("cp.async.commit_group;");

    for (int kt = 0; kt < GKITERS; kt++) {
        asm volatile("cp.async.wait_group 0;");
        __syncthreads();
        if (kt + 1 < GKITERS) {
            load_stage((kt + 1) & 1, kt + 1);
            asm volatile("cp.async.commit_group;");
        }
        int b = kt & 1;
#pragma unroll
        for (int ks = 0; ks < 4; ks++) {
            int kk = ks * 8;
            uint32_t af[4][4], bf[8][2];
#pragma unroll
            for (int mi = 0; mi < 4; mi++) {
                int r0 = wm + mi * 16 + tr;
                af[mi][0] = __float_as_uint(ASM(b, r0,     kk + tc));
                af[mi][1] = __float_as_uint(ASM(b, r0 + 8, kk + tc));
                af[mi][2] = __float_as_uint(ASM(b, r0,     kk + tc + 4));
                af[mi][3] = __float_as_uint(ASM(b, r0 + 8, kk + tc + 4));
            }
#pragma unroll
            for (int ni = 0; ni < 8; ni++) {
                int r0 = wn + ni * 8 + tr;
                bf[ni][0] = __float_as_uint(BSM(b, r0, kk + tc));
                bf[ni][1] = __float_as_uint(BSM(b, r0, kk + tc + 4));
            }
#pragma unroll
            for (int mi = 0; mi < 4; mi++)
#pragma unroll
                for (int ni = 0; ni < 8; ni++) mma_tf32(acc[mi][ni], af[mi], bf[ni]);
        }
    }

#pragma unroll
    for (int mi = 0; mi < 4; mi++) {
        int m = bn + wm + mi * 16 + tr;
        __half* p0 = &g_pairs[(size_t)m * BR];
        __half* p1 = &g_pairs[(size_t)(m + 8) * BR];
#pragma unroll
        for (int ni = 0; ni < 8; ni++) {
            int col = bj + wn + ni * 8 + tc * 2;
            if (col < BR) {
                *(__half2*)(p0 + col) = __floats2half2_rn(acc[mi][ni][0], acc[mi][ni][1]);
                *(__half2*)(p1 + col) = __floats2half2_rn(acc[mi][ni][2], acc[mi][ni][3]);
            }
        }
    }
#undef ASM
#undef BSM
}

// -------- fixup: S = F @ F^T (fp32), 64col x 32row tiles (128 blocks) -------
__global__ __launch_bounds__(256) void fixup_gemm_kernel(const float* __restrict__ F,
                                                         const int* __restrict__ eidx) {
    __shared__ float As[32][33];
    __shared__ float Bs[64][33];
    __shared__ int   s_col[64];
    const int bj = blockIdx.x * 64;
    const int bn = blockIdx.y * 32;
    const int tid = threadIdx.x;
    const int tx = tid & 15, ty = tid >> 4;
    if (tid < 64) s_col[tid] = eidx[bj + tid];
    float acc[2][4] = {};

    for (int k0 = 0; k0 < CH; k0 += 32) {
        {
            int r = tid >> 3;
            int c = (tid & 7) << 2;
            float4 v = *(const float4*)&F[(size_t)(bn + r) * CH + k0 + c];
            As[r][c] = v.x; As[r][c + 1] = v.y; As[r][c + 2] = v.z; As[r][c + 3] = v.w;
        }
#pragma unroll
        for (int l = 0; l < 2; l++) {
            int idx = tid + l * 256;
            int r = idx >> 3;
            int c = (idx & 7) << 2;
            float4 w = *(const float4*)&F[(size_t)(bj + r) * CH + k0 + c];
            Bs[r][c] = w.x; Bs[r][c + 1] = w.y; Bs[r][c + 2] = w.z; Bs[r][c + 3] = w.w;
        }
        __syncthreads();
#pragma unroll
        for (int kk = 0; kk < 32; kk++) {
            float a[2], b[4];
#pragma unroll
            for (int i = 0; i < 2; i++) a[i] = As[ty * 2 + i][kk];
#pragma unroll
            for (int j = 0; j < 4; j++) b[j] = Bs[tx * 4 + j][kk];
#pragma unroll
            for (int i = 0; i < 2; i++)
#pragma unroll
                for (int j = 0; j < 4; j++) acc[i][j] += a[i] * b[j];
        }
        __syncthreads();
    }
#pragma unroll
    for (int i = 0; i < 2; i++) {
        int nrow = bn + ty * 2 + i;
#pragma unroll
        for (int j = 0; j < 4; j++)
            g_pairs[(size_t)nrow * BR + s_col[tx * 4 + j]] = __float2half_rn(acc[i][j]);
    }
}

// ------------------------- helpers ------------------------------------------
__device__ __forceinline__ uint32_t fkey(float v) {
    uint32_t u = __float_as_uint(v);
    return (u & 0x80000000u) ? ~u : (u | 0x80000000u);
}
__device__ __forceinline__ float unfkey(uint32_t u) {
    uint32_t b = (u & 0x80000000u) ? (u & 0x7FFFFFFFu) : ~u;
    return __uint_as_float(b);
}

__device__ __forceinline__ int warpRedInt(int c) {
    return __reduce_add_sync(0xffffffffu, c);
}
__device__ __forceinline__ float warpRedF(float v) {
#pragma unroll
    for (int o = 16; o > 0; o >>= 1) v += __shfl_xor_sync(0xffffffffu, v, o);
    return v;
}

__device__ uint32_t warp_sel_largest_u32(const uint32_t* a, int len, int need) {
    int lane = threadIdx.x & 31;
    uint32_t lo = 0, hi = 0xFFFFFFFFu;
    while (lo < hi) {
        uint32_t d = hi - lo;
        uint32_t mid = lo + (d >> 1) + (d & 1);
        int c = 0;
        for (int i = lane; i < len; i += 32) c += (a[i] >= mid);
        c = warpRedInt(c);
        if (c >= need) lo = mid; else hi = mid - 1;
    }
    return lo;
}
__device__ uint32_t warp_sel_smallest_fkey(const float* a, int len, int need) {
    int lane = threadIdx.x & 31;
    uint32_t lo = 0, hi = 0xFFFFFFFFu;
    while (lo < hi) {
        uint32_t mid = lo + ((hi - lo) >> 1);
        int c = 0;
        for (int i = lane; i < len; i += 32) c += (fkey(a[i]) <= mid);
        c = warpRedInt(c);
        if (c >= need) hi = mid; else lo = mid + 1;
    }
    return lo;
}

__device__ __forceinline__ int blockReduceInt(int c, int* s_red) {
    __syncthreads();
    if (threadIdx.x == 0) *s_red = 0;
    __syncthreads();
    c = warpRedInt(c);
    if ((threadIdx.x & 31) == 0) atomicAdd(s_red, c);
    __syncthreads();
    return *s_red;
}
__device__ __forceinline__ float blockReduceFloat(float v, float* warpBuf) {
    v = warpRedF(v);
    int lane = threadIdx.x & 31, w = threadIdx.x >> 5;
    if (lane == 0) warpBuf[w] = v;
    __syncthreads();
    float s = 0.f;
    if (threadIdx.x == 0)
        for (int i = 0; i < (int)(blockDim.x >> 5); i++) s += warpBuf[i];
    __syncthreads();
    return s;   // thread 0 only
}
__device__ __forceinline__ double blockReduceDouble(double v, double* warpBuf) {
#pragma unroll
    for (int o = 16; o > 0; o >>= 1) v += __shfl_xor_sync(0xffffffffu, v, o);
    int lane = threadIdx.x & 31, w = threadIdx.x >> 5;
    if (lane == 0) warpBuf[w] = v;
    __syncthreads();
    double s = 0.0;
    if (threadIdx.x == 0)
        for (int i = 0; i < (int)(blockDim.x >> 5); i++) s += warpBuf[i];
    __syncthreads();
    return s;   // thread 0 only
}

__device__ __forceinline__ double lterm(float pv, float Eh, float Er) {
    float e = expf(pv);
    return (double)(logf(e + Eh) - pv) + (double)(logf(e + Er) - pv);
}

// ------- fused: hard top-512 + rand 512 + pos-128 + per-row loss ------------
__global__ __launch_bounds__(512) void negsel_kernel(const int* __restrict__ label,
                                                     const float* __restrict__ rnd,
                                                     const int* __restrict__ eidx) {
    __shared__ uint32_t s_negmask[NWORDS];
    __shared__ uint32_t s_posmask[NWORDS];
    __shared__ uint32_t s_listH[CAPN];
    __shared__ u64      s_listR[CAPN];
    __shared__ float    s_pos[MEMSZ];
    __shared__ int      s_cntH, s_cntR, s_red;
    __shared__ float    s_warp[16];
    __shared__ double   s_warpd[16];
    __shared__ uint32_t s_thrP;
    __shared__ float    s_Eh, s_Er;

    const int n = blockIdx.x;
    const int lbl = label[n];
    const __half* row = g_pairs + (size_t)n * BR;
    const float* rrow = rnd + (size_t)n * BR;
    const int tid = threadIdx.x, wid = tid >> 5, lane = tid & 31;

    for (int w = tid; w < NWORDS; w += 512) {
        uint32_t v = g_validbits[w], e = g_eqtab[lbl * 15 + (w % 15)];
        s_negmask[w] = v & ~e;
        s_posmask[w] = v & e;
    }
    for (int i = tid; i < MEMSZ; i += 512) s_pos[i] = INFINITY;
    if (tid == 0) { s_cntH = 0; s_cntR = 0; }
    __syncthreads();
    {   // fold enqueue scatter (redundant with scatter_kernel; harmless)
        int j = eidx[tid];
        uint32_t bit = 1u << (j & 31);
        if (j % CLS == lbl) atomicOr(&s_posmask[j >> 5], bit);
        else                atomicOr(&s_negmask[j >> 5], bit);
    }
    __syncthreads();

    const float thrHs = THR_HARD;
    const float thrRs = THR_RAND;

    // ---- single fused scan (fp16 pairs, fp32 rand) --------------------------
    const __half2* rowh2 = (const __half2*)row;
    for (int q = tid; q < NQ; q += 512) {
        uint32_t nm = (s_negmask[q >> 3] >> ((q & 7) << 2)) & 0xF;
        uint32_t pm = (s_posmask[q >> 3] >> ((q & 7) << 2)) & 0xF;
        if (!(nm | pm)) continue;
        float2 va = __half22float2(rowh2[2 * q]);
        float2 vb = __half22float2(rowh2[2 * q + 1]);
        float vv[4] = {va.x, va.y, vb.x, vb.y};
        int j0 = q << 2;
        if (pm) {
#pragma unroll
            for (int e = 0; e < 4; e++)
                if ((pm >> e) & 1)
                    s_pos[(unsigned)(j0 + e - lbl) / 60u] = vv[e];
        }
        if (nm) {
            float4 r = ((const float4*)rrow)[q];
            float rr[4] = {r.x, r.y, r.z, r.w};
#pragma unroll
            for (int e = 0; e < 4; e++) {
                if ((nm >> e) & 1) {
                    if (vv[e] >= thrHs) {
                        int p = atomicAdd(&s_cntH, 1);
                        if (p < CAPN) s_listH[p] = fkey(vv[e]);
                    }
                    if (rr[e] <= thrRs) {
                        int p = atomicAdd(&s_cntR, 1);
                        if (p < CAPN)
                            s_listR[p] = ((u64)__float_as_uint(rr[e]) << 32) |
                                         (unsigned)(j0 + e);
                    }
                }
            }
        }
    }
    __syncthreads();
    const int cntH = s_cntH, cntR = s_cntR;
    const bool okH = (cntH >= NEGN && cntH <= CAPN);
    const bool okR = (cntR >= NEGN && cntR <= CAPN);

    // ---- warp0: hard thr + Eh; warp1: rand 2-stage + Er; warp2: pos ---------
    if (okH && wid == 0) {
        uint32_t t = warp_sel_largest_u32(s_listH, cntH, NEGN);
        int cg = 0; float se = 0.f;
        for (int i = lane; i < cntH; i += 32) {
            uint32_t u = s_listH[i];
            if (u > t) { cg++; se += expf(unfkey(u)); }
        }
        cg = warpRedInt(cg); se = warpRedF(se);
        if (lane == 0) s_Eh = se + (float)(NEGN - cg) * expf(unfkey(t));
    }
    if (okR && wid == 1) {
        uint32_t lo = 0, hi = 0xFFFFFFFFu;
        while (lo < hi) {
            uint32_t mid = lo + ((hi - lo) >> 1);
            int c = 0;
            for (int i = lane; i < cntR; i += 32)
                c += ((uint32_t)(s_listR[i] >> 32) <= mid);
            c = warpRedInt(c);
            if (c >= NEGN) hi = mid; else lo = mid + 1;
        }
        const uint32_t kv = lo;
        int cl = 0, ce = 0;
        for (int i = lane; i < cntR; i += 32) {
            uint32_t k = (uint32_t)(s_listR[i] >> 32);
            cl += (k < kv); ce += (k == kv);
        }
        cl = warpRedInt(cl); ce = warpRedInt(ce);
        const int need2 = NEGN - cl;
        uint32_t ti = 0xFFFFFFFFu;
        if (ce != need2) {
            uint32_t l2 = 0, h2 = 0xFFFFFFFFu;
            while (l2 < h2) {
                uint32_t mid = l2 + ((h2 - l2) >> 1);
                int c = 0;
                for (int i = lane; i < cntR; i += 32) {
                    u64 w = s_listR[i];
                    c += (((uint32_t)(w >> 32) == kv) && ((uint32_t)w <= mid));
                }
                c = warpRedInt(c);
                if (c >= need2) h2 = mid; else l2 = mid + 1;
            }
            ti = l2;
        }
        float se = 0.f;
        for (int i = lane; i < cntR; i += 32) {
            u64 w = s_listR[i];
            uint32_t k = (uint32_t)(w >> 32);
            if (k < kv || (k == kv && (uint32_t)w <= ti))
                se += expf(__half2float(row[(uint32_t)w]));
        }
        se = warpRedF(se);
        if (lane == 0) s_Er = se;
    }
    if (wid == 2) {
        uint32_t t = warp_sel_smallest_fkey(s_pos, MEMSZ, POSN);
        if (lane == 0) s_thrP = t;
    }
    __syncthreads();

    // ---- rare fallbacks: block-wide bisect over gmem (exactness net) --------
    if (!okH) {
        uint32_t lo = 0, hi = 0xFFFFFFFFu;
        while (lo < hi) {
            uint32_t d = hi - lo;
            uint32_t mid = lo + (d >> 1) + (d & 1);
            int c = 0;
            for (int j = tid; j < BR; j += 512)
                if ((s_negmask[j >> 5] >> (j & 31)) & 1)
                    c += (fkey(__half2float(row[j])) >= mid);
            c = blockReduceInt(c, &s_red);
            if (c >= NEGN) lo = mid; else hi = mid - 1;
        }
        uint32_t t = lo;
        int cg = 0; float se = 0.f;
        for (int j = tid; j < BR; j += 512)
            if ((s_negmask[j >> 5] >> (j & 31)) & 1) {
                float x = __half2float(row[j]);
                if (fkey(x) > t) { cg++; se += expf(x); }
            }
        cg = blockReduceInt(cg, &s_red);
        float tot = blockReduceFloat(se, s_warp);
        if (tid == 0) s_Eh = tot + (float)(NEGN - cg) * expf(unfkey(t));
        __syncthreads();
    }
    if (!okR) {
        u64 lo = 0ull, hi = 0xFFFFFFFFFFFFFFFFull;
        while (lo < hi) {
            u64 mid = lo + ((hi - lo) >> 1);
            int c = 0;
            for (int j = tid; j < BR; j += 512)
                if ((s_negmask[j >> 5] >> (j & 31)) & 1) {
                    u64 w = ((u64)__float_as_uint(rrow[j]) << 32) | (unsigned)j;
                    c += (w <= mid);
                }
            c = blockReduceInt(c, &s_red);
            if (c >= NEGN) hi = mid; else lo = mid + 1;
        }
        const u64 t = lo;
        float se = 0.f;
        for (int j = tid; j < BR; j += 512)
            if ((s_negmask[j >> 5] >> (j & 31)) & 1) {
                u64 w = ((u64)__float_as_uint(rrow[j]) << 32) | (unsigned)j;
                if (w <= t) se += expf(__half2float(row[j]));
            }
        float tot = blockReduceFloat(se, s_warp);
        if (tid == 0) s_Er = tot;
        __syncthreads();
    }

    // ---- per-row loss: 128 smallest pos values (with ties) ------------------
    const float Eh = s_Eh, Er = s_Er;
    const uint32_t tP = s_thrP;
    int c = 0; double ts = 0.0;
    for (int i = tid; i < MEMSZ; i += 512) {
        float pv = s_pos[i];
        if (fkey(pv) < tP) { c++; ts += lterm(pv, Eh, Er); }
    }
    c = blockReduceInt(c, &s_red);
    double tsum = blockReduceDouble(ts, s_warpd);
    if (tid == 0) {
        tsum += (double)(POSN - c) * lterm(unfkey(tP), Eh, Er);
        atomicAdd(&g_loss, tsum);
    }
}

__global__ void finalize_kernel(float* out) {
    out[0] = (float)(g_loss / (double)(BATCH * 2 * POSN));
}

// ------------------------- launcher -----------------------------------------
extern "C" void kernel_launch(void* const* d_in, const int* in_sizes, int n_in,
                              void* d_out, int out_size) {
    const float* f    = (const float*)d_in[0];
    const int*   lab  = (const int*)d_in[1];
    const int*   eidx = (const int*)d_in[2];
    const float* bank = (const float*)d_in[3];
    const float* flag = (const float*)d_in[4];
    const float* rnd  = (const float*)d_in[5];
    float* out = (float*)d_out;

    const int GEMM_SMEM = 2 * 2 * GBM * GPAD * 4;   // 73728 bytes
    cudaFuncSetAttribute(gemm_tf32_kernel,
                         cudaFuncAttributeMaxDynamicSharedMemorySize, GEMM_SMEM);

    prep_kernel<<<6, 256>>>(flag);
    scatter_kernel<<<2, 256>>>(eidx);
    gemm_tf32_kernel<<<dim3((BR + GBN - 1) / GBN, BATCH / GBM), 128, GEMM_SMEM>>>(f, bank);
    fixup_gemm_kernel<<<dim3(BATCH / 64, BATCH / 32), 256>>>(f, eidx);
    negsel_kernel<<<BATCH, 512>>>(lab, rnd, eidx);
    finalize_kernel<<<1, 1>>>(out);
    (void)in_sizes; (void)n_in; (void)out_size;
}

// round 16
// speedup vs baseline: 2.5699x; 1.0336x over previous
#include <cuda_runtime.h>
#include <cuda_fp16.h>
#include <cuda_bf16.h>
#include <math.h>
#include <stdint.h>

#define BATCH 512
#define CH    256
#define CLS   60
#define MEMSZ 684
#define BR    41040
#define POSN  128
#define NEGN  512
#define NWORDS 1283          // ceil(BR/32)
#define CAPN  2048
#define NQ    (BR/4)         // 10260 4-elem groups per row

#define THR_HARD 0.12f
#define THR_RAND 0.0155f

typedef unsigned long long u64;

// ------------------------- device scratch -----------------------------------
__device__ __half          g_pairs[(size_t)BATCH * BR];   // 42 MB (fp16 logits)
__device__ __nv_bfloat16   g_bankh[(size_t)BR * CH];      // 21 MB bf16 bank
__device__ __nv_bfloat16   g_fh[BATCH * CH];              // bf16 features
__device__ uint32_t        g_validbits[NWORDS];
__device__ uint32_t        g_eqtab[CLS * 15];
__device__ double          g_loss;

// ------------------------- prep ---------------------------------------------
__global__ void prep_kernel(const float* __restrict__ flag) {
    int i = blockIdx.x * blockDim.x + threadIdx.x;
    if (i == 0) g_loss = 0.0;
    if (i < CLS * 15) {
        int lbl = i / 15, p = i % 15;
        int off = (32 * p) % 60;
        uint32_t m = 0;
        for (int b = 0; b < 32; b++) if ((off + b) % 60 == lbl) m |= 1u << b;
        g_eqtab[i] = m;
    }
    if (i < NWORDS) {
        uint32_t m = 0; int base = i * 32;
        for (int b = 0; b < 32; b++) {
            int j = base + b;
            if (j < BR && flag[j] > 0.f) m |= 1u << b;
        }
        g_validbits[i] = m;
    }
}

__global__ void scatter_kernel(const int* __restrict__ eidx) {
    int m = blockIdx.x * blockDim.x + threadIdx.x;
    if (m < BATCH) { int j = eidx[m]; atomicOr(&g_validbits[j >> 5], 1u << (j & 31)); }
}

// ------- convert F and bank to bf16 (vectorized float4 -> 4x bf16) ----------
#define BANK_F4 ((BR * CH) / 4)      // 2626560
#define F_F4    ((BATCH * CH) / 4)   // 32768
__global__ __launch_bounds__(256) void tobf16_kernel(const float* __restrict__ F,
                                                     const float* __restrict__ B) {
    int idx = blockIdx.x * blockDim.x + threadIdx.x;
    int stride = gridDim.x * blockDim.x;
    for (int i = idx; i < BANK_F4 + F_F4; i += stride) {
        if (i < BANK_F4) {
            float4 v = ((const float4*)B)[i];
            __nv_bfloat16* d = g_bankh + (size_t)i * 4;
            d[0] = __float2bfloat16(v.x); d[1] = __float2bfloat16(v.y);
            d[2] = __float2bfloat16(v.z); d[3] = __float2bfloat16(v.w);
        } else {
            int k = i - BANK_F4;
            float4 v = ((const float4*)F)[k];
            __nv_bfloat16* d = g_fh + (size_t)k * 4;
            d[0] = __float2bfloat16(v.x); d[1] = __float2bfloat16(v.y);
            d[2] = __float2bfloat16(v.z); d[3] = __float2bfloat16(v.w);
        }
    }
}

// ------------------------- bf16 tensor-core GEMM ----------------------------
// P[512,41040] = F @ bank^T, bf16 inputs, fp32 accum, fp16 output.
// Block 128x128, BK=32 (bf16), 128 threads = 4 warps (2x2), warp 64x64.
#define GBM 128
#define GBN 128
#define GBK 32
#define GPADH 40             // bf16 units per smem row (80 B)
#define GKITERS 8

__device__ __forceinline__ void mma_bf16(float* c, const uint32_t* a, const uint32_t* b) {
    asm volatile(
        "mma.sync.aligned.m16n8k16.row.col.f32.bf16.bf16.f32 "
        "{%0,%1,%2,%3},{%4,%5,%6,%7},{%8,%9},{%0,%1,%2,%3};"
        : "+f"(c[0]), "+f"(c[1]), "+f"(c[2]), "+f"(c[3])
        : "r"(a[0]), "r"(a[1]), "r"(a[2]), "r"(a[3]), "r"(b[0]), "r"(b[1]));
}

__global__ __launch_bounds__(128) void gemm_bf16_kernel() {
    extern __shared__ __nv_bfloat16 smh[];
    __nv_bfloat16* As = smh;                        // [2][128][40]
    __nv_bfloat16* Bs = smh + 2 * GBM * GPADH;      // [2][128][40]
#define AS32(bf, r, c) (*(const uint32_t*)&As[(bf) * GBM * GPADH + (r) * GPADH + (c)])
#define BS32(bf, r, c) (*(const uint32_t*)&Bs[(bf) * GBM * GPADH + (r) * GPADH + (c)])

    const int bj = blockIdx.x * GBN;
    const int bn = blockIdx.y * GBM;
    const int tid = threadIdx.x;
    const int wid = tid >> 5, lane = tid & 31;
    const int wm = (wid >> 1) * 64, wn = (wid & 1) * 64;
    const int tr = lane >> 2, tc = lane & 3;

    float acc[4][8][4];
#pragma unroll
    for (int i = 0; i < 4; i++)
#pragma unroll
        for (int j = 0; j < 8; j++)
#pragma unroll
            for (int k = 0; k < 4; k++) acc[i][j][k] = 0.f;

    auto load_stage = [&](int buf, int kt) {
        int k0 = kt * GBK;
        // A: 128 rows x 4 chunks (16B = 8 bf16): 512 slots / 128 thr = 4 each
#pragma unroll
        for (int i = 0; i < 4; i++) {
            int slot = tid + i * 128;
            int r = slot >> 2;
            int c8 = (slot & 3) * 8;
            uint32_t da = (uint32_t)__cvta_generic_to_shared(
                &As[(size_t)buf * GBM * GPADH + r * GPADH + c8]);
            const __nv_bfloat16* ga = g_fh + (size_t)(bn + r) * CH + k0 + c8;
            asm volatile("cp.async.cg.shared.global [%0], [%1], 16;" :: "r"(da), "l"(ga));
            int j = bj + r;
            int ok = (j < BR) ? 16 : 0;
            const __nv_bfloat16* gb = g_bankh + (size_t)(j < BR ? j : 0) * CH + k0 + c8;
            uint32_t db = (uint32_t)__cvta_generic_to_shared(
                &Bs[(size_t)buf * GBM * GPADH + r * GPADH + c8]);
            asm volatile("cp.async.cg.shared.global [%0], [%1], 16, %2;" :: "r"(db), "l"(gb), "r"(ok));
        }
    };

    load_stage(0, 0);
    asm volatile("cp.async.commit_group;");

    for (int kt = 0; kt < GKITERS; kt++) {
        asm volatile("cp.async.wait_group 0;");
        __syncthreads();
        if (kt + 1 < GKITERS) {
            load_stage((kt + 1) & 1, kt + 1);
            asm volatile("cp.async.commit_group;");
        }
        int b = kt & 1;
#pragma unroll
        for (int ks = 0; ks < 2; ks++) {          // two k16 steps per BK=32
            int kk = ks * 16;
            uint32_t af[4][4], bfr[8][2];
#pragma unroll
            for (int mi = 0; mi < 4; mi++) {
                int r0 = wm + mi * 16 + tr;
                af[mi][0] = AS32(b, r0,     kk + 2 * tc);
                af[mi][1] = AS32(b, r0 + 8, kk + 2 * tc);
                af[mi][2] = AS32(b, r0,     kk + 2 * tc + 8);
                af[mi][3] = AS32(b, r0 + 8, kk + 2 * tc + 8);
            }
#pragma unroll
            for (int ni = 0; ni < 8; ni++) {
                int r0 = wn + ni * 8 + tr;
                bfr[ni][0] = BS32(b, r0, kk + 2 * tc);
                bfr[ni][1] = BS32(b, r0, kk + 2 * tc + 8);
            }
#pragma unroll
            for (int mi = 0; mi < 4; mi++)
#pragma unroll
                for (int ni = 0; ni < 8; ni++) mma_bf16(acc[mi][ni], af[mi], bfr[ni]);
        }
    }

#pragma unroll
    for (int mi = 0; mi < 4; mi++) {
        int m = bn + wm + mi * 16 + tr;
        __half* p0 = &g_pairs[(size_t)m * BR];
        __half* p1 = &g_pairs[(size_t)(m + 8) * BR];
#pragma unroll
        for (int ni = 0; ni < 8; ni++) {
            int col = bj + wn + ni * 8 + tc * 2;
            if (col < BR) {
                *(__half2*)(p0 + col) = __floats2half2_rn(acc[mi][ni][0], acc[mi][ni][1]);
                *(__half2*)(p1 + col) = __floats2half2_rn(acc[mi][ni][2], acc[mi][ni][3]);
            }
        }
    }
#undef AS32
#undef BS32
}

// -------- fixup: S = F @ F^T (fp32), 64col x 32row tiles (128 blocks) -------
__global__ __launch_bounds__(256) void fixup_gemm_kernel(const float* __restrict__ F,
                                                         const int* __restrict__ eidx) {
    __shared__ float As[32][33];
    __shared__ float Bs[64][33];
    __shared__ int   s_col[64];
    const int bj = blockIdx.x * 64;
    const int bn = blockIdx.y * 32;
    const int tid = threadIdx.x;
    const int tx = tid & 15, ty = tid >> 4;
    if (tid < 64) s_col[tid] = eidx[bj + tid];
    float acc[2][4] = {};

    for (int k0 = 0; k0 < CH; k0 += 32) {
        {
            int r = tid >> 3;
            int c = (tid & 7) << 2;
            float4 v = *(const float4*)&F[(size_t)(bn + r) * CH + k0 + c];
            As[r][c] = v.x; As[r][c + 1] = v.y; As[r][c + 2] = v.z; As[r][c + 3] = v.w;
        }
#pragma unroll
        for (int l = 0; l < 2; l++) {
            int idx = tid + l * 256;
            int r = idx >> 3;
            int c = (idx & 7) << 2;
            float4 w = *(const float4*)&F[(size_t)(bj + r) * CH + k0 + c];
            Bs[r][c] = w.x; Bs[r][c + 1] = w.y; Bs[r][c + 2] = w.z; Bs[r][c + 3] = w.w;
        }
        __syncthreads();
#pragma unroll
        for (int kk = 0; kk < 32; kk++) {
            float a[2], b[4];
#pragma unroll
            for (int i = 0; i < 2; i++) a[i] = As[ty * 2 + i][kk];
#pragma unroll
            for (int j = 0; j < 4; j++) b[j] = Bs[tx * 4 + j][kk];
#pragma unroll
            for (int i = 0; i < 2; i++)
#pragma unroll
                for (int j = 0; j < 4; j++) acc[i][j] += a[i] * b[j];
        }
        __syncthreads();
    }
#pragma unroll
    for (int i = 0; i < 2; i++) {
        int nrow = bn + ty * 2 + i;
#pragma unroll
        for (int j = 0; j < 4; j++)
            g_pairs[(size_t)nrow * BR + s_col[tx * 4 + j]] = __float2half_rn(acc[i][j]);
    }
}

// ------------------------- helpers ------------------------------------------
__device__ __forceinline__ uint32_t fkey(float v) {
    uint32_t u = __float_as_uint(v);
    return (u & 0x80000000u) ? ~u : (u | 0x80000000u);
}
__device__ __forceinline__ float unfkey(uint32_t u) {
    uint32_t b = (u & 0x80000000u) ? (u & 0x7FFFFFFFu) : ~u;
    return __uint_as_float(b);
}

__device__ __forceinline__ int warpRedInt(int c) {
    return __reduce_add_sync(0xffffffffu, c);
}
__device__ __forceinline__ float warpRedF(float v) {
#pragma unroll
    for (int o = 16; o > 0; o >>= 1) v += __shfl_xor_sync(0xffffffffu, v, o);
    return v;
}

__device__ uint32_t warp_sel_largest_u32(const uint32_t* a, int len, int need) {
    int lane = threadIdx.x & 31;
    uint32_t lo = 0, hi = 0xFFFFFFFFu;
    while (lo < hi) {
        uint32_t d = hi - lo;
        uint32_t mid = lo + (d >> 1) + (d & 1);
        int c = 0;
        for (int i = lane; i < len; i += 32) c += (a[i] >= mid);
        c = warpRedInt(c);
        if (c >= need) lo = mid; else hi = mid - 1;
    }
    return lo;
}
__device__ uint32_t warp_sel_smallest_fkey(const float* a, int len, int need) {
    int lane = threadIdx.x & 31;
    uint32_t lo = 0, hi = 0xFFFFFFFFu;
    while (lo < hi) {
        uint32_t mid = lo + ((hi - lo) >> 1);
        int c = 0;
        for (int i = lane; i < len; i += 32) c += (fkey(a[i]) <= mid);
        c = warpRedInt(c);
        if (c >= need) hi = mid; else lo = mid + 1;
    }
    return lo;
}

__device__ __forceinline__ int blockReduceInt(int c, int* s_red) {
    __syncthreads();
    if (threadIdx.x == 0) *s_red = 0;
    __syncthreads();
    c = warpRedInt(c);
    if ((threadIdx.x & 31) == 0) atomicAdd(s_red, c);
    __syncthreads();
    return *s_red;
}
__device__ __forceinline__ float blockReduceFloat(float v, float* warpBuf) {
    v = warpRedF(v);
    int lane = threadIdx.x & 31, w = threadIdx.x >> 5;
    if (lane == 0) warpBuf[w] = v;
    __syncthreads();
    float s = 0.f;
    if (threadIdx.x == 0)
        for (int i = 0; i < (int)(blockDim.x >> 5); i++) s += warpBuf[i];
    __syncthreads();
    return s;
}
__device__ __forceinline__ double blockReduceDouble(double v, double* warpBuf) {
#pragma unroll
    for (int o = 16; o > 0; o >>= 1) v += __shfl_xor_sync(0xffffffffu, v, o);
    int lane = threadIdx.x & 31, w = threadIdx.x >> 5;
    if (lane == 0) warpBuf[w] = v;
    __syncthreads();
    double s = 0.0;
    if (threadIdx.x == 0)
        for (int i = 0; i < (int)(blockDim.x >> 5); i++) s += warpBuf[i];
    __syncthreads();
    return s;
}

__device__ __forceinline__ double lterm(float pv, float Eh, float Er) {
    float e = expf(pv);
    return (double)(logf(e + Eh) - pv) + (double)(logf(e + Er) - pv);
}

// ------- fused: hard top-512 + rand 512 + pos-128 + per-row loss ------------
__global__ __launch_bounds__(512) void negsel_kernel(const int* __restrict__ label,
                                                     const float* __restrict__ rnd,
                                                     const int* __restrict__ eidx) {
    __shared__ uint32_t s_negmask[NWORDS];
    __shared__ uint32_t s_posmask[NWORDS];
    __shared__ uint32_t s_listH[CAPN];
    __shared__ u64      s_listR[CAPN];
    __shared__ float    s_pos[MEMSZ];
    __shared__ int      s_cntH, s_cntR, s_red;
    __shared__ float    s_warp[16];
    __shared__ double   s_warpd[16];
    __shared__ uint32_t s_thrP;
    __shared__ float    s_Eh, s_Er;

    const int n = blockIdx.x;
    const int lbl = label[n];
    const __half* row = g_pairs + (size_t)n * BR;
    const float* rrow = rnd + (size_t)n * BR;
    const int tid = threadIdx.x, wid = tid >> 5, lane = tid & 31;

    for (int w = tid; w < NWORDS; w += 512) {
        uint32_t v = g_validbits[w], e = g_eqtab[lbl * 15 + (w % 15)];
        s_negmask[w] = v & ~e;
        s_posmask[w] = v & e;
    }
    for (int i = tid; i < MEMSZ; i += 512) s_pos[i] = INFINITY;
    if (tid == 0) { s_cntH = 0; s_cntR = 0; }
    __syncthreads();
    {
        int j = eidx[tid];
        uint32_t bit = 1u << (j & 31);
        if (j % CLS == lbl) atomicOr(&s_posmask[j >> 5], bit);
        else                atomicOr(&s_negmask[j >> 5], bit);
    }
    __syncthreads();

    const float thrHs = THR_HARD;
    const float thrRs = THR_RAND;

    // ---- single fused scan (fp16 pairs, fp32 rand) --------------------------
    const __half2* rowh2 = (const __half2*)row;
    for (int q = tid; q < NQ; q += 512) {
        uint32_t nm = (s_negmask[q >> 3] >> ((q & 7) << 2)) & 0xF;
        uint32_t pm = (s_posmask[q >> 3] >> ((q & 7) << 2)) & 0xF;
        if (!(nm | pm)) continue;
        float2 va = __half22float2(rowh2[2 * q]);
        float2 vb = __half22float2(rowh2[2 * q + 1]);
        float vv[4] = {va.x, va.y, vb.x, vb.y};
        int j0 = q << 2;
        if (pm) {
#pragma unroll
            for (int e = 0; e < 4; e++)
                if ((pm >> e) & 1)
                    s_pos[(unsigned)(j0 + e - lbl) / 60u] = vv[e];
        }
        if (nm) {
            float4 r = ((const float4*)rrow)[q];
            float rr[4] = {r.x, r.y, r.z, r.w};
#pragma unroll
            for (int e = 0; e < 4; e++) {
                if ((nm >> e) & 1) {
                    if (vv[e] >= thrHs) {
                        int p = atomicAdd(&s_cntH, 1);
                        if (p < CAPN) s_listH[p] = fkey(vv[e]);
                    }
                    if (rr[e] <= thrRs) {
                        int p = atomicAdd(&s_cntR, 1);
                        if (p < CAPN)
                            s_listR[p] = ((u64)__float_as_uint(rr[e]) << 32) |
                                         (unsigned)(j0 + e);
                    }
                }
            }
        }
    }
    __syncthreads();
    const int cntH = s_cntH, cntR = s_cntR;
    const bool okH = (cntH >= NEGN && cntH <= CAPN);
    const bool okR = (cntR >= NEGN && cntR <= CAPN);

    // ---- warp0: hard thr + Eh; warp1: rand 2-stage + Er; warp2: pos ---------
    if (okH && wid == 0) {
        uint32_t t = warp_sel_largest_u32(s_listH, cntH, NEGN);
        int cg = 0; float se = 0.f;
        for (int i = lane; i < cntH; i += 32) {
            uint32_t u = s_listH[i];
            if (u > t) { cg++; se += expf(unfkey(u)); }
        }
        cg = warpRedInt(cg); se = warpRedF(se);
        if (lane == 0) s_Eh = se + (float)(NEGN - cg) * expf(unfkey(t));
    }
    if (okR && wid == 1) {
        uint32_t lo = 0, hi = 0xFFFFFFFFu;
        while (lo < hi) {
            uint32_t mid = lo + ((hi - lo) >> 1);
            int c = 0;
            for (int i = lane; i < cntR; i += 32)
                c += ((uint32_t)(s_listR[i] >> 32) <= mid);
            c = warpRedInt(c);
            if (c >= NEGN) hi = mid; else lo = mid + 1;
        }
        const uint32_t kv = lo;
        int cl = 0, ce = 0;
        for (int i = lane; i < cntR; i += 32) {
            uint32_t k = (uint32_t)(s_listR[i] >> 32);
            cl += (k < kv); ce += (k == kv);
        }
        cl = warpRedInt(cl); ce = warpRedInt(ce);
        const int need2 = NEGN - cl;
        uint32_t ti = 0xFFFFFFFFu;
        if (ce != need2) {
            uint32_t l2 = 0, h2 = 0xFFFFFFFFu;
            while (l2 < h2) {
                uint32_t mid = l2 + ((h2 - l2) >> 1);
                int c = 0;
                for (int i = lane; i < cntR; i += 32) {
                    u64 w = s_listR[i];
                    c += (((uint32_t)(w >> 32) == kv) && ((uint32_t)w <= mid));
                }
                c = warpRedInt(c);
                if (c >= need2) h2 = mid; else l2 = mid + 1;
            }
            ti = l2;
        }
        float se = 0.f;
        for (int i = lane; i < cntR; i += 32) {
            u64 w = s_listR[i];
            uint32_t k = (uint32_t)(w >> 32);
            if (k < kv || (k == kv && (uint32_t)w <= ti))
                se += expf(__half2float(row[(uint32_t)w]));
        }
        se = warpRedF(se);
        if (lane == 0) s_Er = se;
    }
    if (wid == 2) {
        uint32_t t = warp_sel_smallest_fkey(s_pos, MEMSZ, POSN);
        if (lane == 0) s_thrP = t;
    }
    __syncthreads();

    // ---- rare fallbacks: block-wide bisect over gmem (exactness net) --------
    if (!okH) {
        uint32_t lo = 0, hi = 0xFFFFFFFFu;
        while (lo < hi) {
            uint32_t d = hi - lo;
            uint32_t mid = lo + (d >> 1) + (d & 1);
            int c = 0;
            for (int j = tid; j < BR; j += 512)
                if ((s_negmask[j >> 5] >> (j & 31)) & 1)
                    c += (fkey(__half2float(row[j])) >= mid);
            c = blockReduceInt(c, &s_red);
            if (c >= NEGN) lo = mid; else hi = mid - 1;
        }
        uint32_t t = lo;
        int cg = 0; float se = 0.f;
        for (int j = tid; j < BR; j += 512)
            if ((s_negmask[j >> 5] >> (j & 31)) & 1) {
                float x = __half2float(row[j]);
                if (fkey(x) > t) { cg++; se += expf(x); }
            }
        cg = blockReduceInt(cg, &s_red);
        float tot = blockReduceFloat(se, s_warp);
        if (tid == 0) s_Eh = tot + (float)(NEGN - cg) * expf(unfkey(t));
        __syncthreads();
    }
    if (!okR) {
        u64 lo = 0ull, hi = 0xFFFFFFFFFFFFFFFFull;
        while (lo < hi) {
            u64 mid = lo + ((hi - lo) >> 1);
            int c = 0;
            for (int j = tid; j < BR; j += 512)
                if ((s_negmask[j >> 5] >> (j & 31)) & 1) {
                    u64 w = ((u64)__float_as_uint(rrow[j]) << 32) | (unsigned)j;
                    c += (w <= mid);
                }
            c = blockReduceInt(c, &s_red);
            if (c >= NEGN) hi = mid; else lo = mid + 1;
        }
        const u64 t = lo;
        float se = 0.f;
        for (int j = tid; j < BR; j += 512)
            if ((s_negmask[j >> 5] >> (j & 31)) & 1) {
                u64 w = ((u64)__float_as_uint(rrow[j]) << 32) | (unsigned)j;
                if (w <= t) se += expf(__half2float(row[j]));
            }
        float tot = blockReduceFloat(se, s_warp);
        if (tid == 0) s_Er = tot;
        __syncthreads();
    }

    // ---- per-row loss: 128 smallest pos values (with ties) ------------------
    const float Eh = s_Eh, Er = s_Er;
    const uint32_t tP = s_thrP;
    int c = 0; double ts = 0.0;
    for (int i = tid; i < MEMSZ; i += 512) {
        float pv = s_pos[i];
        if (fkey(pv) < tP) { c++; ts += lterm(pv, Eh, Er); }
    }
    c = blockReduceInt(c, &s_red);
    double tsum = blockReduceDouble(ts, s_warpd);
    if (tid == 0) {
        tsum += (double)(POSN - c) * lterm(unfkey(tP), Eh, Er);
        atomicAdd(&g_loss, tsum);
    }
}

__global__ void finalize_kernel(float* out) {
    out[0] = (float)(g_loss / (double)(BATCH * 2 * POSN));
}

// ------------------------- launcher -----------------------------------------
extern "C" void kernel_launch(void* const* d_in, const int* in_sizes, int n_in,
                              void* d_out, int out_size) {
    const float* f    = (const float*)d_in[0];
    const int*   lab  = (const int*)d_in[1];
    const int*   eidx = (const int*)d_in[2];
    const float* bank = (const float*)d_in[3];
    const float* flag = (const float*)d_in[4];
    const float* rnd  = (const float*)d_in[5];
    float* out = (float*)d_out;

    const int GEMM_SMEM = 2 * 2 * GBM * GPADH * 2;   // 40960 bytes (bf16)
    cudaFuncSetAttribute(gemm_bf16_kernel,
                         cudaFuncAttributeMaxDynamicSharedMemorySize, GEMM_SMEM);

    prep_kernel<<<6, 256>>>(flag);
    scatter_kernel<<<2, 256>>>(eidx);
    tobf16_kernel<<<1184, 256>>>(f, bank);
    gemm_bf16_kernel<<<dim3((BR + GBN - 1) / GBN, BATCH / GBM), 128, GEMM_SMEM>>>();
    fixup_gemm_kernel<<<dim3(BATCH / 64, BATCH / 32), 256>>>(f, eidx);
    negsel_kernel<<<BATCH, 512>>>(lab, rnd, eidx);
    finalize_kernel<<<1, 1>>>(out);
    (void)in_sizes; (void)n_in; (void)out_size;
}

// round 17
// speedup vs baseline: 2.6494x; 1.0309x over previous
#include <cuda_runtime.h>
#include <cuda_fp16.h>
#include <cuda_bf16.h>
#include <math.h>
#include <stdint.h>

#define BATCH 512
#define CH    256
#define CLS   60
#define MEMSZ 684
#define BR    41040
#define POSN  128
#define NEGN  512
#define NWORDS 1283          // ceil(BR/32)
#define CAPN  2048
#define NQ    (BR/4)         // 10260 4-elem groups per row

#define THR_HARD 0.12f
#define THR_RAND 0.0155f

typedef unsigned long long u64;

// ------------------------- device scratch -----------------------------------
__device__ __half          g_pairs[(size_t)BATCH * BR];   // 42 MB (fp16 logits)
__device__ __nv_bfloat16   g_bankh[(size_t)BR * CH];      // 21 MB bf16 bank
__device__ __nv_bfloat16   g_fh[BATCH * CH];              // bf16 features
__device__ uint32_t        g_validbits[NWORDS];
__device__ uint32_t        g_eqtab[CLS * 15];
__device__ double          g_loss;

// ------------------------- prep ---------------------------------------------
__global__ void prep_kernel(const float* __restrict__ flag) {
    int i = blockIdx.x * blockDim.x + threadIdx.x;
    if (i == 0) g_loss = 0.0;
    if (i < CLS * 15) {
        int lbl = i / 15, p = i % 15;
        int off = (32 * p) % 60;
        uint32_t m = 0;
        for (int b = 0; b < 32; b++) if ((off + b) % 60 == lbl) m |= 1u << b;
        g_eqtab[i] = m;
    }
    if (i < NWORDS) {
        uint32_t m = 0; int base = i * 32;
        for (int b = 0; b < 32; b++) {
            int j = base + b;
            if (j < BR && flag[j] > 0.f) m |= 1u << b;
        }
        g_validbits[i] = m;
    }
}

__global__ void scatter_kernel(const int* __restrict__ eidx) {
    int m = blockIdx.x * blockDim.x + threadIdx.x;
    if (m < BATCH) { int j = eidx[m]; atomicOr(&g_validbits[j >> 5], 1u << (j & 31)); }
}

// ------- convert F and bank to bf16 (vectorized float4 -> 4x bf16) ----------
#define BANK_F4 ((BR * CH) / 4)      // 2626560
#define F_F4    ((BATCH * CH) / 4)   // 32768
__global__ __launch_bounds__(256) void tobf16_kernel(const float* __restrict__ F,
                                                     const float* __restrict__ B) {
    int idx = blockIdx.x * blockDim.x + threadIdx.x;
    int stride = gridDim.x * blockDim.x;
    for (int i = idx; i < BANK_F4 + F_F4; i += stride) {
        if (i < BANK_F4) {
            float4 v = ((const float4*)B)[i];
            __nv_bfloat16* d = g_bankh + (size_t)i * 4;
            d[0] = __float2bfloat16(v.x); d[1] = __float2bfloat16(v.y);
            d[2] = __float2bfloat16(v.z); d[3] = __float2bfloat16(v.w);
        } else {
            int k = i - BANK_F4;
            float4 v = ((const float4*)F)[k];
            __nv_bfloat16* d = g_fh + (size_t)k * 4;
            d[0] = __float2bfloat16(v.x); d[1] = __float2bfloat16(v.y);
            d[2] = __float2bfloat16(v.z); d[3] = __float2bfloat16(v.w);
        }
    }
}

// ------------------------- bf16 tensor-core GEMM ----------------------------
// P[512,41040] = F @ bank^T, bf16 in, fp32 accum, fp16 out.
// Block 128x128, BK=32, 256 threads = 8 warps (2M x 4N), warp tile 64x32.
#define GBM 128
#define GBN 128
#define GBK 32
#define GPADH 40             // bf16 units per smem row (80 B)
#define GKITERS 8

__device__ __forceinline__ void mma_bf16(float* c, const uint32_t* a, const uint32_t* b) {
    asm volatile(
        "mma.sync.aligned.m16n8k16.row.col.f32.bf16.bf16.f32 "
        "{%0,%1,%2,%3},{%4,%5,%6,%7},{%8,%9},{%0,%1,%2,%3};"
        : "+f"(c[0]), "+f"(c[1]), "+f"(c[2]), "+f"(c[3])
        : "r"(a[0]), "r"(a[1]), "r"(a[2]), "r"(a[3]), "r"(b[0]), "r"(b[1]));
}

__global__ __launch_bounds__(256, 2) void gemm_bf16_kernel() {
    extern __shared__ __nv_bfloat16 smh[];
    __nv_bfloat16* As = smh;                        // [2][128][40]
    __nv_bfloat16* Bs = smh + 2 * GBM * GPADH;      // [2][128][40]
#define AS32(bf, r, c) (*(const uint32_t*)&As[(bf) * GBM * GPADH + (r) * GPADH + (c)])
#define BS32(bf, r, c) (*(const uint32_t*)&Bs[(bf) * GBM * GPADH + (r) * GPADH + (c)])

    const int bj = blockIdx.x * GBN;
    const int bn = blockIdx.y * GBM;
    const int tid = threadIdx.x;
    const int wid = tid >> 5, lane = tid & 31;
    const int wm = (wid >> 2) * 64;      // 0,64
    const int wn = (wid & 3) * 32;       // 0,32,64,96
    const int tr = lane >> 2, tc = lane & 3;

    float acc[4][4][4];
#pragma unroll
    for (int i = 0; i < 4; i++)
#pragma unroll
        for (int j = 0; j < 4; j++)
#pragma unroll
            for (int k = 0; k < 4; k++) acc[i][j][k] = 0.f;

    auto load_stage = [&](int buf, int kt) {
        int k0 = kt * GBK;
        // A/B: 128 rows x 4 chunks (16B = 8 bf16) = 512 slots / 256 thr = 2 each
#pragma unroll
        for (int i = 0; i < 2; i++) {
            int slot = tid + i * 256;
            int r = slot >> 2;
            int c8 = (slot & 3) * 8;
            uint32_t da = (uint32_t)__cvta_generic_to_shared(
                &As[(size_t)buf * GBM * GPADH + r * GPADH + c8]);
            const __nv_bfloat16* ga = g_fh + (size_t)(bn + r) * CH + k0 + c8;
            asm volatile("cp.async.cg.shared.global [%0], [%1], 16;" :: "r"(da), "l"(ga));
            int j = bj + r;
            int ok = (j < BR) ? 16 : 0;
            const __nv_bfloat16* gb = g_bankh + (size_t)(j < BR ? j : 0) * CH + k0 + c8;
            uint32_t db = (uint32_t)__cvta_generic_to_shared(
                &Bs[(size_t)buf * GBM * GPADH + r * GPADH + c8]);
            asm volatile("cp.async.cg.shared.global [%0], [%1], 16, %2;" :: "r"(db), "l"(gb), "r"(ok));
        }
    };

    load_stage(0, 0);
    asm volatile("cp.async.commit_group;");

    for (int kt = 0; kt < GKITERS; kt++) {
        asm volatile("cp.async.wait_group 0;");
        __syncthreads();
        if (kt + 1 < GKITERS) {
            load_stage((kt + 1) & 1, kt + 1);
            asm volatile("cp.async.commit_group;");
        }
        int b = kt & 1;
#pragma unroll
        for (int ks = 0; ks < 2; ks++) {          // two k16 steps per BK=32
            int kk = ks * 16;
            uint32_t af[4][4], bfr[4][2];
#pragma unroll
            for (int mi = 0; mi < 4; mi++) {
                int r0 = wm + mi * 16 + tr;
                af[mi][0] = AS32(b, r0,     kk + 2 * tc);
                af[mi][1] = AS32(b, r0 + 8, kk + 2 * tc);
                af[mi][2] = AS32(b, r0,     kk + 2 * tc + 8);
                af[mi][3] = AS32(b, r0 + 8, kk + 2 * tc + 8);
            }
#pragma unroll
            for (int ni = 0; ni < 4; ni++) {
                int r0 = wn + ni * 8 + tr;
                bfr[ni][0] = BS32(b, r0, kk + 2 * tc);
                bfr[ni][1] = BS32(b, r0, kk + 2 * tc + 8);
            }
#pragma unroll
            for (int mi = 0; mi < 4; mi++)
#pragma unroll
                for (int ni = 0; ni < 4; ni++) mma_bf16(acc[mi][ni], af[mi], bfr[ni]);
        }
    }

#pragma unroll
    for (int mi = 0; mi < 4; mi++) {
        int m = bn + wm + mi * 16 + tr;
        __half* p0 = &g_pairs[(size_t)m * BR];
        __half* p1 = &g_pairs[(size_t)(m + 8) * BR];
#pragma unroll
        for (int ni = 0; ni < 4; ni++) {
            int col = bj + wn + ni * 8 + tc * 2;
            if (col < BR) {
                *(__half2*)(p0 + col) = __floats2half2_rn(acc[mi][ni][0], acc[mi][ni][1]);
                *(__half2*)(p1 + col) = __floats2half2_rn(acc[mi][ni][2], acc[mi][ni][3]);
            }
        }
    }
#undef AS32
#undef BS32
}

// -------- fixup: S = F @ F^T (fp32), 64col x 32row tiles (128 blocks) -------
__global__ __launch_bounds__(256) void fixup_gemm_kernel(const float* __restrict__ F,
                                                         const int* __restrict__ eidx) {
    __shared__ float As[32][33];
    __shared__ float Bs[64][33];
    __shared__ int   s_col[64];
    const int bj = blockIdx.x * 64;
    const int bn = blockIdx.y * 32;
    const int tid = threadIdx.x;
    const int tx = tid & 15, ty = tid >> 4;
    if (tid < 64) s_col[tid] = eidx[bj + tid];
    float acc[2][4] = {};

    for (int k0 = 0; k0 < CH; k0 += 32) {
        {
            int r = tid >> 3;
            int c = (tid & 7) << 2;
            float4 v = *(const float4*)&F[(size_t)(bn + r) * CH + k0 + c];
            As[r][c] = v.x; As[r][c + 1] = v.y; As[r][c + 2] = v.z; As[r][c + 3] = v.w;
        }
#pragma unroll
        for (int l = 0; l < 2; l++) {
            int idx = tid + l * 256;
            int r = idx >> 3;
            int c = (idx & 7) << 2;
            float4 w = *(const float4*)&F[(size_t)(bj + r) * CH + k0 + c];
            Bs[r][c] = w.x; Bs[r][c + 1] = w.y; Bs[r][c + 2] = w.z; Bs[r][c + 3] = w.w;
        }
        __syncthreads();
#pragma unroll
        for (int kk = 0; kk < 32; kk++) {
            float a[2], b[4];
#pragma unroll
            for (int i = 0; i < 2; i++) a[i] = As[ty * 2 + i][kk];
#pragma unroll
            for (int j = 0; j < 4; j++) b[j] = Bs[tx * 4 + j][kk];
#pragma unroll
            for (int i = 0; i < 2; i++)
#pragma unroll
                for (int j = 0; j < 4; j++) acc[i][j] += a[i] * b[j];
        }
        __syncthreads();
    }
#pragma unroll
    for (int i = 0; i < 2; i++) {
        int nrow = bn + ty * 2 + i;
#pragma unroll
        for (int j = 0; j < 4; j++)
            g_pairs[(size_t)nrow * BR + s_col[tx * 4 + j]] = __float2half_rn(acc[i][j]);
    }
}

// ------------------------- helpers ------------------------------------------
__device__ __forceinline__ uint32_t fkey(float v) {
    uint32_t u = __float_as_uint(v);
    return (u & 0x80000000u) ? ~u : (u | 0x80000000u);
}
__device__ __forceinline__ float unfkey(uint32_t u) {
    uint32_t b = (u & 0x80000000u) ? (u & 0x7FFFFFFFu) : ~u;
    return __uint_as_float(b);
}

__device__ __forceinline__ int warpRedInt(int c) {
    return __reduce_add_sync(0xffffffffu, c);
}
__device__ __forceinline__ float warpRedF(float v) {
#pragma unroll
    for (int o = 16; o > 0; o >>= 1) v += __shfl_xor_sync(0xffffffffu, v, o);
    return v;
}

__device__ uint32_t warp_sel_largest_u32(const uint32_t* a, int len, int need) {
    int lane = threadIdx.x & 31;
    uint32_t lo = 0, hi = 0xFFFFFFFFu;
    while (lo < hi) {
        uint32_t d = hi - lo;
        uint32_t mid = lo + (d >> 1) + (d & 1);
        int c = 0;
        for (int i = lane; i < len; i += 32) c += (a[i] >= mid);
        c = warpRedInt(c);
        if (c >= need) lo = mid; else hi = mid - 1;
    }
    return lo;
}
__device__ uint32_t warp_sel_smallest_fkey(const float* a, int len, int need) {
    int lane = threadIdx.x & 31;
    uint32_t lo = 0, hi = 0xFFFFFFFFu;
    while (lo < hi) {
        uint32_t mid = lo + ((hi - lo) >> 1);
        int c = 0;
        for (int i = lane; i < len; i += 32) c += (fkey(a[i]) <= mid);
        c = warpRedInt(c);
        if (c >= need) hi = mid; else lo = mid + 1;
    }
    return lo;
}

__device__ __forceinline__ int blockReduceInt(int c, int* s_red) {
    __syncthreads();
    if (threadIdx.x == 0) *s_red = 0;
    __syncthreads();
    c = warpRedInt(c);
    if ((threadIdx.x & 31) == 0) atomicAdd(s_red, c);
    __syncthreads();
    return *s_red;
}
__device__ __forceinline__ float blockReduceFloat(float v, float* warpBuf) {
    v = warpRedF(v);
    int lane = threadIdx.x & 31, w = threadIdx.x >> 5;
    if (lane == 0) warpBuf[w] = v;
    __syncthreads();
    float s = 0.f;
    if (threadIdx.x == 0)
        for (int i = 0; i < (int)(blockDim.x >> 5); i++) s += warpBuf[i];
    __syncthreads();
    return s;
}
__device__ __forceinline__ double blockReduceDouble(double v, double* warpBuf) {
#pragma unroll
    for (int o = 16; o > 0; o >>= 1) v += __shfl_xor_sync(0xffffffffu, v, o);
    int lane = threadIdx.x & 31, w = threadIdx.x >> 5;
    if (lane == 0) warpBuf[w] = v;
    __syncthreads();
    double s = 0.0;
    if (threadIdx.x == 0)
        for (int i = 0; i < (int)(blockDim.x >> 5); i++) s += warpBuf[i];
    __syncthreads();
    return s;
}

__device__ __forceinline__ double lterm(float pv, float Eh, float Er) {
    float e = expf(pv);
    return (double)(logf(e + Eh) - pv) + (double)(logf(e + Er) - pv);
}

// ------- fused: hard top-512 + rand 512 + pos-128 + per-row loss ------------
__global__ __launch_bounds__(512) void negsel_kernel(const int* __restrict__ label,
                                                     const float* __restrict__ rnd,
                                                     const int* __restrict__ eidx) {
    __shared__ uint32_t s_negmask[NWORDS];
    __shared__ uint32_t s_posmask[NWORDS];
    __shared__ uint32_t s_listH[CAPN];
    __shared__ u64      s_listR[CAPN];
    __shared__ float    s_pos[MEMSZ];
    __shared__ int      s_cntH, s_cntR, s_red;
    __shared__ float    s_warp[16];
    __shared__ double   s_warpd[16];
    __shared__ uint32_t s_thrP;
    __shared__ float    s_Eh, s_Er;

    const int n = blockIdx.x;
    const int lbl = label[n];
    const __half* row = g_pairs + (size_t)n * BR;
    const float* rrow = rnd + (size_t)n * BR;
    const int tid = threadIdx.x, wid = tid >> 5, lane = tid & 31;

    for (int w = tid; w < NWORDS; w += 512) {
        uint32_t v = g_validbits[w], e = g_eqtab[lbl * 15 + (w % 15)];
        s_negmask[w] = v & ~e;
        s_posmask[w] = v & e;
    }
    for (int i = tid; i < MEMSZ; i += 512) s_pos[i] = INFINITY;
    if (tid == 0) { s_cntH = 0; s_cntR = 0; }
    __syncthreads();
    {
        int j = eidx[tid];
        uint32_t bit = 1u << (j & 31);
        if (j % CLS == lbl) atomicOr(&s_posmask[j >> 5], bit);
        else                atomicOr(&s_negmask[j >> 5], bit);
    }
    __syncthreads();

    const float thrHs = THR_HARD;
    const float thrRs = THR_RAND;

    // ---- single fused scan (fp16 pairs, fp32 rand) --------------------------
    const __half2* rowh2 = (const __half2*)row;
    for (int q = tid; q < NQ; q += 512) {
        uint32_t nm = (s_negmask[q >> 3] >> ((q & 7) << 2)) & 0xF;
        uint32_t pm = (s_posmask[q >> 3] >> ((q & 7) << 2)) & 0xF;
        if (!(nm | pm)) continue;
        float2 va = __half22float2(rowh2[2 * q]);
        float2 vb = __half22float2(rowh2[2 * q + 1]);
        float vv[4] = {va.x, va.y, vb.x, vb.y};
        int j0 = q << 2;
        if (pm) {
#pragma unroll
            for (int e = 0; e < 4; e++)
                if ((pm >> e) & 1)
                    s_pos[(unsigned)(j0 + e - lbl) / 60u] = vv[e];
        }
        if (nm) {
            float4 r = ((const float4*)rrow)[q];
            float rr[4] = {r.x, r.y, r.z, r.w};
#pragma unroll
            for (int e = 0; e < 4; e++) {
                if ((nm >> e) & 1) {
                    if (vv[e] >= thrHs) {
                        int p = atomicAdd(&s_cntH, 1);
                        if (p < CAPN) s_listH[p] = fkey(vv[e]);
                    }
                    if (rr[e] <= thrRs) {
                        int p = atomicAdd(&s_cntR, 1);
                        if (p < CAPN)
                            s_listR[p] = ((u64)__float_as_uint(rr[e]) << 32) |
                                         (unsigned)(j0 + e);
                    }
                }
            }
        }
    }
    __syncthreads();
    const int cntH = s_cntH, cntR = s_cntR;
    const bool okH = (cntH >= NEGN && cntH <= CAPN);
    const bool okR = (cntR >= NEGN && cntR <= CAPN);

    // ---- warp0: hard thr + Eh; warp1: rand 2-stage + Er; warp2: pos ---------
    if (okH && wid == 0) {
        uint32_t t = warp_sel_largest_u32(s_listH, cntH, NEGN);
        int cg = 0; float se = 0.f;
        for (int i = lane; i < cntH; i += 32) {
            uint32_t u = s_listH[i];
            if (u > t) { cg++; se += expf(unfkey(u)); }
        }
        cg = warpRedInt(cg); se = warpRedF(se);
        if (lane == 0) s_Eh = se + (float)(NEGN - cg) * expf(unfkey(t));
    }
    if (okR && wid == 1) {
        uint32_t lo = 0, hi = 0xFFFFFFFFu;
        while (lo < hi) {
            uint32_t mid = lo + ((hi - lo) >> 1);
            int c = 0;
            for (int i = lane; i < cntR; i += 32)
                c += ((uint32_t)(s_listR[i] >> 32) <= mid);
            c = warpRedInt(c);
            if (c >= NEGN) hi = mid; else lo = mid + 1;
        }
        const uint32_t kv = lo;
        int cl = 0, ce = 0;
        for (int i = lane; i < cntR; i += 32) {
            uint32_t k = (uint32_t)(s_listR[i] >> 32);
            cl += (k < kv); ce += (k == kv);
        }
        cl = warpRedInt(cl); ce = warpRedInt(ce);
        const int need2 = NEGN - cl;
        uint32_t ti = 0xFFFFFFFFu;
        if (ce != need2) {
            uint32_t l2 = 0, h2 = 0xFFFFFFFFu;
            while (l2 < h2) {
                uint32_t mid = l2 + ((h2 - l2) >> 1);
                int c = 0;
                for (int i = lane; i < cntR; i += 32) {
                    u64 w = s_listR[i];
                    c += (((uint32_t)(w >> 32) == kv) && ((uint32_t)w <= mid));
                }
                c = warpRedInt(c);
                if (c >= need2) h2 = mid; else l2 = mid + 1;
            }
            ti = l2;
        }
        float se = 0.f;
        for (int i = lane; i < cntR; i += 32) {
            u64 w = s_listR[i];
            uint32_t k = (uint32_t)(w >> 32);
            if (k < kv || (k == kv && (uint32_t)w <= ti))
                se += expf(__half2float(row[(uint32_t)w]));
        }
        se = warpRedF(se);
        if (lane == 0) s_Er = se;
    }
    if (wid == 2) {
        uint32_t t = warp_sel_smallest_fkey(s_pos, MEMSZ, POSN);
        if (lane == 0) s_thrP = t;
    }
    __syncthreads();

    // ---- rare fallbacks: block-wide bisect over gmem (exactness net) --------
    if (!okH) {
        uint32_t lo = 0, hi = 0xFFFFFFFFu;
        while (lo < hi) {
            uint32_t d = hi - lo;
            uint32_t mid = lo + (d >> 1) + (d & 1);
            int c = 0;
            for (int j = tid; j < BR; j += 512)
                if ((s_negmask[j >> 5] >> (j & 31)) & 1)
                    c += (fkey(__half2float(row[j])) >= mid);
            c = blockReduceInt(c, &s_red);
            if (c >= NEGN) lo = mid; else hi = mid - 1;
        }
        uint32_t t = lo;
        int cg = 0; float se = 0.f;
        for (int j = tid; j < BR; j += 512)
            if ((s_negmask[j >> 5] >> (j & 31)) & 1) {
                float x = __half2float(row[j]);
                if (fkey(x) > t) { cg++; se += expf(x); }
            }
        cg = blockReduceInt(cg, &s_red);
        float tot = blockReduceFloat(se, s_warp);
        if (tid == 0) s_Eh = tot + (float)(NEGN - cg) * expf(unfkey(t));
        __syncthreads();
    }
    if (!okR) {
        u64 lo = 0ull, hi = 0xFFFFFFFFFFFFFFFFull;
        while (lo < hi) {
            u64 mid = lo + ((hi - lo) >> 1);
            int c = 0;
            for (int j = tid; j < BR; j += 512)
                if ((s_negmask[j >> 5] >> (j & 31)) & 1) {
                    u64 w = ((u64)__float_as_uint(rrow[j]) << 32) | (unsigned)j;
                    c += (w <= mid);
                }
            c = blockReduceInt(c, &s_red);
            if (c >= NEGN) hi = mid; else lo = mid + 1;
        }
        const u64 t = lo;
        float se = 0.f;
        for (int j = tid; j < BR; j += 512)
            if ((s_negmask[j >> 5] >> (j & 31)) & 1) {
                u64 w = ((u64)__float_as_uint(rrow[j]) << 32) | (unsigned)j;
                if (w <= t) se += expf(__half2float(row[j]));
            }
        float tot = blockReduceFloat(se, s_warp);
        if (tid == 0) s_Er = tot;
        __syncthreads();
    }

    // ---- per-row loss: 128 smallest pos values (with ties) ------------------
    const float Eh = s_Eh, Er = s_Er;
    const uint32_t tP = s_thrP;
    int c = 0; double ts = 0.0;
    for (int i = tid; i < MEMSZ; i += 512) {
        float pv = s_pos[i];
        if (fkey(pv) < tP) { c++; ts += lterm(pv, Eh, Er); }
    }
    c = blockReduceInt(c, &s_red);
    double tsum = blockReduceDouble(ts, s_warpd);
    if (tid == 0) {
        tsum += (double)(POSN - c) * lterm(unfkey(tP), Eh, Er);
        atomicAdd(&g_loss, tsum);
    }
}

__global__ void finalize_kernel(float* out) {
    out[0] = (float)(g_loss / (double)(BATCH * 2 * POSN));
}

// ------------------------- launcher -----------------------------------------
extern "C" void kernel_launch(void* const* d_in, const int* in_sizes, int n_in,
                              void* d_out, int out_size) {
    const float* f    = (const float*)d_in[0];
    const int*   lab  = (const int*)d_in[1];
    const int*   eidx = (const int*)d_in[2];
    const float* bank = (const float*)d_in[3];
    const float* flag = (const float*)d_in[4];
    const float* rnd  = (const float*)d_in[5];
    float* out = (float*)d_out;

    const int GEMM_SMEM = 2 * 2 * GBM * GPADH * 2;   // 40960 bytes (bf16)
    cudaFuncSetAttribute(gemm_bf16_kernel,
                         cudaFuncAttributeMaxDynamicSharedMemorySize, GEMM_SMEM);

    prep_kernel<<<6, 256>>>(flag);
    scatter_kernel<<<2, 256>>>(eidx);
    tobf16_kernel<<<1184, 256>>>(f, bank);
    gemm_bf16_kernel<<<dim3((BR + GBN - 1) / GBN, BATCH / GBM), 256, GEMM_SMEM>>>();
    fixup_gemm_kernel<<<dim3(BATCH / 64, BATCH / 32), 256>>>(f, eidx);
    negsel_kernel<<<BATCH, 512>>>(lab, rnd, eidx);
    finalize_kernel<<<1, 1>>>(out);
    (void)in_sizes; (void)n_in; (void)out_size;
}